// round 8
// baseline (speedup 1.0000x reference)
#include <cuda_runtime.h>
#include <cuda_bf16.h>
#include <stdint.h>

// Problem constants
#define NN      8192
#define GEV     32
#define PER     256      // nodes per event
#define KK      15
#define FIN     4
#define FOUT    4
#define LATD    64
#define HIDD    128

#define H_ELEMS   (NN * LATD)          // 524288
#define XE_ELEMS  (NN * FOUT)          // 32768
#define NKE       (NN * KK)            // 122880
#define XE_OFF    (H_ELEMS)
#define EI_OFF    (H_ELEMS + XE_ELEMS) // 557056

#define FULLMASK 0xffffffffu

// Device scratch (no allocations allowed)
__device__ float g_h0[NN * LATD];
__device__ float g_h1[NN * LATD];
__device__ int   g_nbr[NN * KK];

// ---------------------------------------------------------------------------
// Kernel 1: space_emb FFN  h = leaky(x@W1+b1)@W2+b2
// 4 threads per row, each owns 16 output columns. grid 128 x 256.
// ---------------------------------------------------------------------------
__global__ void k_space_emb(const float* __restrict__ x,
                            const float* __restrict__ W1, const float* __restrict__ b1,
                            const float* __restrict__ W2, const float* __restrict__ b2,
                            float* __restrict__ hout) {
    __shared__ float sW1[FIN * LATD];
    __shared__ float sb1[LATD];
    __shared__ float sW2[LATD * LATD];
    __shared__ float sb2[LATD];
    int tid = threadIdx.x;
    for (int i = tid; i < FIN * LATD; i += blockDim.x) sW1[i] = W1[i];
    for (int i = tid; i < LATD; i += blockDim.x) { sb1[i] = b1[i]; sb2[i] = b2[i]; }
    {
        float4* sW24 = (float4*)sW2;
        const float4* W24 = (const float4*)W2;
#pragma unroll
        for (int i = 0; i < (LATD * LATD) / 4 / 256; ++i)
            sW24[tid + i * 256] = W24[tid + i * 256];
    }
    __syncthreads();

    int row = blockIdx.x * 64 + (tid >> 2);
    int q   = tid & 3;
    int c0  = q * 16;

    float xi0 = x[row * FIN + 0];
    float xi1 = x[row * FIN + 1];
    float xi2 = x[row * FIN + 2];
    float xi3 = x[row * FIN + 3];

    float acc[16];
#pragma unroll
    for (int c = 0; c < 16; ++c) acc[c] = sb2[c0 + c];

#pragma unroll 4
    for (int j = 0; j < LATD; ++j) {
        float tj = sb1[j]
                 + xi0 * sW1[0 * LATD + j]
                 + xi1 * sW1[1 * LATD + j]
                 + xi2 * sW1[2 * LATD + j]
                 + xi3 * sW1[3 * LATD + j];
        tj = (tj > 0.0f) ? tj : 0.01f * tj;
        const float* w2r = &sW2[j * LATD + c0];
#pragma unroll
        for (int c = 0; c < 16; ++c) acc[c] += tj * w2r[c];
    }
    float* o = &hout[row * LATD + c0];
#pragma unroll
    for (int c = 0; c < 16; ++c) o[c] = acc[c];
}

// ---------------------------------------------------------------------------
// Kernel 2: event-local kNN (k=15) on h[:, :3].
// 4 blocks per event, 64 queries per block, 256 threads: 4 threads per query
// (candidate stride 4), each keeps a sorted top-15 (uint8 local indices);
// two lexicographic (d, idx) merge rounds — matches lax.top_k tie-breaking.
// ---------------------------------------------------------------------------
__global__ void __launch_bounds__(256, 1)
k_knn(const float* __restrict__ h,
      int* __restrict__ nbr,
      float* __restrict__ out_ei) {
    __shared__ float   px[PER], py[PER], pz[PER];
    __shared__ float   mdA[256][KK];
    __shared__ uint8_t miA[256][KK];
    __shared__ float   mdB[128][KK];
    __shared__ uint8_t miB[128][KK];

    int tid  = threadIdx.x;           // 0..255
    int ev   = blockIdx.x >> 2;
    int quad = blockIdx.x & 3;
    int base = ev * PER;

    {
        int n = tid;
        px[n] = h[(base + n) * LATD + 0];
        py[n] = h[(base + n) * LATD + 1];
        pz[n] = h[(base + n) * LATD + 2];
    }
    __syncthreads();

    int lq  = quad * 64 + (tid >> 2);  // local query index in event
    int sub = tid & 3;                 // candidate residue

    float bd[KK];
    int   bi[KK];
#pragma unroll
    for (int s = 0; s < KK; ++s) { bd[s] = 3.0e38f; bi[s] = 0; }

    float xi = px[lq], yi = py[lq], zi = pz[lq];

    for (int j = sub; j < PER; j += 4) {
        float dx = __fadd_rn(xi, -px[j]);
        float dy = __fadd_rn(yi, -py[j]);
        float dz = __fadd_rn(zi, -pz[j]);
        float d  = __fadd_rn(__fadd_rn(__fmul_rn(dx, dx), __fmul_rn(dy, dy)),
                             __fmul_rn(dz, dz));
        if (j == lq) d = 3.3e38f;            // exclude self
        if (d < bd[KK - 1]) {
#pragma unroll
            for (int p = KK - 1; p >= 0; --p) {
                bool shift = (p > 0) && (d < bd[p - 1]);
                bool place = !shift && (d < bd[p]);
                if (shift)      { bd[p] = bd[p - 1]; bi[p] = bi[p - 1]; }
                else if (place) { bd[p] = d;         bi[p] = j;         }
            }
        }
    }
#pragma unroll
    for (int s = 0; s < KK; ++s) { mdA[tid][s] = bd[s]; miA[tid][s] = (uint8_t)bi[s]; }
    __syncthreads();

    // merge round 1: 128 threads, pairwise (sub 0,1) and (sub 2,3)
    if (tid < 128) {
        int q    = tid >> 1;
        int half = tid & 1;
        int ra = q * 4 + 2 * half, rb = ra + 1;
        int a = 0, b = 0;
#pragma unroll
        for (int s = 0; s < KK; ++s) {
            float da = mdA[ra][a], db = mdA[rb][b];
            int   ia = miA[ra][a], ib = miA[rb][b];
            bool takeA = (da < db) || (da == db && ia < ib);
            if (takeA) { mdB[tid][s] = da; miB[tid][s] = (uint8_t)ia; ++a; }
            else       { mdB[tid][s] = db; miB[tid][s] = (uint8_t)ib; ++b; }
        }
    }
    __syncthreads();

    // merge round 2: 64 threads, final output
    if (tid < 64) {
        int gid = base + quad * 64 + tid;
        float fgid = (float)gid;
        int ra = 2 * tid, rb = 2 * tid + 1;
        int a = 0, b = 0;
#pragma unroll
        for (int s = 0; s < KK; ++s) {
            float da = mdB[ra][a], db = mdB[rb][b];
            int   ia = miB[ra][a], ib = miB[rb][b];
            bool takeA = (da < db) || (da == db && ia < ib);
            int  pick  = takeA ? ia : ib;
            if (takeA) ++a; else ++b;
            int gj = base + pick;
            int e  = gid * KK + s;
            nbr[e] = gj;
            out_ei[e]       = (float)gj;
            out_ei[NKE + e] = fgid;
        }
    }
}

// ---------------------------------------------------------------------------
// Kernel 3: GIN layer, 512 threads / 32 rows / grid 256, occupancy 2 (32
// warps/SM). m kept ROW-MAJOR in smem; activation reads are warp-broadcast
// LDS.128, weight reads LDS.64/LDS.32. Slim tiles keep regs <= 64.
// FUSE_OE epilogue reuses m (as sh) and st (as su).
// ---------------------------------------------------------------------------
#define M_S  68    // m / sh row stride (64 + pad)
#define ST_S 132   // st / su row stride (128 + pad)

template <bool FUSE_OE>
__global__ void __launch_bounds__(512, 2)
k_gin(const float* __restrict__ h_in,
      float* __restrict__ h_out,
      const int* __restrict__ nbr,
      const float* __restrict__ Wa, const float* __restrict__ ba,
      const float* __restrict__ Wb, const float* __restrict__ bb,
      const float* __restrict__ W1o, const float* __restrict__ b1o,
      const float* __restrict__ W2o, const float* __restrict__ b2o,
      float* __restrict__ xe) {
    extern __shared__ float sm[];
    float* sWa  = sm;                    // 8192
    float* sWb  = sWa + 8192;            // 8192
    float* sba  = sWb + 8192;            // 128
    float* sbb  = sba + 128;             // 64
    float* m    = sbb + 64;              // 32*M_S = 2176 (reused as sh for OE)
    float* st   = m + 32 * M_S;          // 32*ST_S = 4224 (reused as su)
    float* sW1o = st + 32 * ST_S;        // 4096 (FUSE_OE)
    float* sW2o = sW1o + 4096;           // 256
    float* sb1o = sW2o + 256;            // 64
    float* sb2o = sb1o + 64;             // 4

    int tid = threadIdx.x;
    // ---- stage weights (row-major, vectorized) -----------------------------
    {
        const float4* Wa4 = (const float4*)Wa;
        const float4* Wb4 = (const float4*)Wb;
        float4* dA = (float4*)sWa;
        float4* dB = (float4*)sWb;
#pragma unroll
        for (int i = 0; i < 4; ++i) {
            dA[tid + i * 512] = Wa4[tid + i * 512];
            dB[tid + i * 512] = Wb4[tid + i * 512];
        }
        if (tid < 128) sba[tid] = ba[tid];
        else if (tid >= 128 && tid < 192) sbb[tid - 128] = bb[tid - 128];
        if (FUSE_OE) {
            const float4* W1o4 = (const float4*)W1o;
            float4* d3 = (float4*)sW1o;
#pragma unroll
            for (int i = 0; i < 2; ++i) d3[tid + i * 512] = W1o4[tid + i * 512];
            if (tid >= 192 && tid < 448) sW2o[tid - 192] = W2o[tid - 192];
            if (tid >= 448 && tid < 512) sb1o[tid - 448] = b1o[tid - 448];
            if (tid < 4) sb2o[tid] = b2o[tid];
        }
    }

    int base = blockIdx.x * 32;

    // ---- Gather: m = h_i + sum of 15 neighbors (row-major) -----------------
    {
        int r = tid >> 4;                // 0..31
        int q = tid & 15;                // float4 quarter
        int i = base + r;
        const float4* h4 = (const float4*)h_in;
        const int* nb = &nbr[i * KK];
        float4 a = h4[i * 16 + q];
#pragma unroll
        for (int s = 0; s < KK; ++s) {
            int j = nb[s];
            float4 v = h4[j * 16 + q];
            a.x += v.x; a.y += v.y; a.z += v.z; a.w += v.w;
        }
        *(float4*)&m[r * M_S + q * 4] = a;
    }
    __syncthreads();

    int rg = tid >> 6;                  // 0..7 (warp-pair uniform)
    int r0 = rg * 4;
    int cx = tid & 63;

    // ---- Phase B: t = relu(m @ Wa + ba), thread tile 4 rows x 2 cols -------
    {
        int c1 = cx * 2;
        float acc[4][2];
#pragma unroll
        for (int i = 0; i < 4; ++i) { acc[i][0] = sba[c1]; acc[i][1] = sba[c1 + 1]; }

#pragma unroll 4
        for (int k = 0; k < 64; k += 4) {
            float2 b0 = *(const float2*)&sWa[(k + 0) * HIDD + c1];
            float2 b1 = *(const float2*)&sWa[(k + 1) * HIDD + c1];
            float2 b2 = *(const float2*)&sWa[(k + 2) * HIDD + c1];
            float2 b3 = *(const float2*)&sWa[(k + 3) * HIDD + c1];
#pragma unroll
            for (int i = 0; i < 4; ++i) {
                float4 a = *(const float4*)&m[(r0 + i) * M_S + k];   // broadcast
                acc[i][0] += a.x * b0.x + a.y * b1.x + a.z * b2.x + a.w * b3.x;
                acc[i][1] += a.x * b0.y + a.y * b1.y + a.z * b2.y + a.w * b3.y;
            }
        }
#pragma unroll
        for (int i = 0; i < 4; ++i) {
            float2 q;
            q.x = fmaxf(acc[i][0], 0.f);
            q.y = fmaxf(acc[i][1], 0.f);
            *(float2*)&st[(r0 + i) * ST_S + c1] = q;
        }
    }
    __syncthreads();

    // ---- Phase C: h_out = h_in + t @ Wb + bb, thread tile 4 rows x 1 col ---
    int c = cx;
    {
        float acc2[4];
#pragma unroll
        for (int i = 0; i < 4; ++i) acc2[i] = sbb[c];

#pragma unroll 4
        for (int k = 0; k < 128; k += 4) {
            float b0 = sWb[(k + 0) * LATD + c];
            float b1 = sWb[(k + 1) * LATD + c];
            float b2 = sWb[(k + 2) * LATD + c];
            float b3 = sWb[(k + 3) * LATD + c];
#pragma unroll
            for (int i = 0; i < 4; ++i) {
                float4 a = *(const float4*)&st[(r0 + i) * ST_S + k]; // broadcast
                acc2[i] += a.x * b0 + a.y * b1 + a.z * b2 + a.w * b3;
            }
        }
#pragma unroll
        for (int i = 0; i < 4; ++i) {
            float o = h_in[(base + r0 + i) * LATD + c] + acc2[i];
            h_out[(base + r0 + i) * LATD + c] = o;
            if (FUSE_OE) m[(r0 + i) * M_S + c] = o;                  // sh = m reuse
        }
    }

    if (FUSE_OE) {
        __syncthreads();
        // ---- OE1: u = leaky(h @ W1o + b1o), thread tile 4 rows x 1 col -----
        float u[4];
#pragma unroll
        for (int i = 0; i < 4; ++i) u[i] = sb1o[c];
#pragma unroll 4
        for (int k = 0; k < 64; k += 4) {
            float b0 = sW1o[(k + 0) * LATD + c];
            float b1 = sW1o[(k + 1) * LATD + c];
            float b2 = sW1o[(k + 2) * LATD + c];
            float b3 = sW1o[(k + 3) * LATD + c];
#pragma unroll
            for (int i = 0; i < 4; ++i) {
                float4 a = *(const float4*)&m[(r0 + i) * M_S + k];   // broadcast
                u[i] += a.x * b0 + a.y * b1 + a.z * b2 + a.w * b3;
            }
        }
#pragma unroll
        for (int i = 0; i < 4; ++i) {
            float q = (u[i] > 0.f) ? u[i] : 0.01f * u[i];
            st[(r0 + i) * ST_S + c] = q;                             // su = st reuse
        }
        __syncthreads();
        // ---- OE2: x_emb = u @ W2o + b2o; 128 threads = (row, feature) ------
        if (tid < 128) {
            int row = tid >> 2;
            int oc  = tid & 3;
            float a = sb2o[oc];
#pragma unroll 8
            for (int k = 0; k < LATD; ++k)
                a += st[row * ST_S + k] * sW2o[k * FOUT + oc];
            xe[(base + row) * FOUT + oc] = a;
        }
    }
}

// ---------------------------------------------------------------------------
extern "C" void kernel_launch(void* const* d_in, const int* in_sizes, int n_in,
                              void* d_out, int out_size) {
    const float* x     = (const float*)d_in[0];
    const float* W_se1 = (const float*)d_in[3];
    const float* b_se1 = (const float*)d_in[4];
    const float* W_se2 = (const float*)d_in[5];
    const float* b_se2 = (const float*)d_in[6];
    const float* W_g1a = (const float*)d_in[7];
    const float* b_g1a = (const float*)d_in[8];
    const float* W_g1b = (const float*)d_in[9];
    const float* b_g1b = (const float*)d_in[10];
    const float* W_g2a = (const float*)d_in[11];
    const float* b_g2a = (const float*)d_in[12];
    const float* W_g2b = (const float*)d_in[13];
    const float* b_g2b = (const float*)d_in[14];
    const float* W_oe1 = (const float*)d_in[15];
    const float* b_oe1 = (const float*)d_in[16];
    const float* W_oe2 = (const float*)d_in[17];
    const float* b_oe2 = (const float*)d_in[18];

    float* out    = (float*)d_out;
    float* out_h  = out;
    float* out_xe = out + XE_OFF;
    float* out_ei = out + EI_OFF;

    void *p_h0, *p_h1, *p_nbr;
    cudaGetSymbolAddress(&p_h0, g_h0);
    cudaGetSymbolAddress(&p_h1, g_h1);
    cudaGetSymbolAddress(&p_nbr, g_nbr);
    float* h0 = (float*)p_h0;
    float* h1 = (float*)p_h1;
    int*   nb = (int*)p_nbr;

    static const size_t gin_smem_base =
        (size_t)(8192 + 8192 + 128 + 64 + 32 * M_S + 32 * ST_S) * sizeof(float);
    static const size_t gin_smem_oe = gin_smem_base +
        (size_t)(4096 + 256 + 64 + 4) * sizeof(float);
    cudaFuncSetAttribute(k_gin<false>, cudaFuncAttributeMaxDynamicSharedMemorySize,
                         (int)gin_smem_base);
    cudaFuncSetAttribute(k_gin<true>, cudaFuncAttributeMaxDynamicSharedMemorySize,
                         (int)gin_smem_oe);

    // 1) space_emb -> h0
    k_space_emb<<<NN / 64, 256>>>(x, W_se1, b_se1, W_se2, b_se2, h0);
    // 2) kNN on h0[:, :3] -> nbr, ei written to output
    k_knn<<<GEV * 4, 256>>>(h0, nb, out_ei);
    // 3) GIN layer 1: h0 -> h1
    k_gin<false><<<NN / 32, 512, gin_smem_base>>>(h0, h1, nb,
        W_g1a, b_g1a, W_g1b, b_g1b, nullptr, nullptr, nullptr, nullptr, nullptr);
    // 4) GIN layer 2 + fused out_emb: h1 -> d_out (h), x_emb -> d_out
    k_gin<true><<<NN / 32, 512, gin_smem_oe>>>(h1, out_h, nb,
        W_g2a, b_g2a, W_g2b, b_g2b, W_oe1, b_oe1, W_oe2, b_oe2, out_xe);
}

// round 9
// speedup vs baseline: 1.0339x; 1.0339x over previous
#include <cuda_runtime.h>
#include <cuda_bf16.h>
#include <stdint.h>

// Problem constants
#define NN      8192
#define GEV     32
#define PER     256      // nodes per event
#define KK      15
#define FIN     4
#define FOUT    4
#define LATD    64
#define HIDD    128

#define H_ELEMS   (NN * LATD)          // 524288
#define XE_ELEMS  (NN * FOUT)          // 32768
#define NKE       (NN * KK)            // 122880
#define XE_OFF    (H_ELEMS)
#define EI_OFF    (H_ELEMS + XE_ELEMS) // 557056

#define FULLMASK 0xffffffffu

typedef unsigned long long ull;

// packed f32x2 helpers (FFMA2 path — only reachable via PTX fma.rn.f32x2)
__device__ __forceinline__ ull pk2(float lo, float hi) {
    ull d; asm("mov.b64 %0, {%1, %2};" : "=l"(d) : "f"(lo), "f"(hi)); return d;
}
__device__ __forceinline__ void upk2(float& lo, float& hi, ull v) {
    asm("mov.b64 {%0, %1}, %2;" : "=f"(lo), "=f"(hi) : "l"(v));
}
__device__ __forceinline__ ull f2fma(ull a, ull b, ull c) {
    ull d; asm("fma.rn.f32x2 %0, %1, %2, %3;" : "=l"(d) : "l"(a), "l"(b), "l"(c));
    return d;
}

// Device scratch (no allocations allowed)
__device__ float g_h0[NN * LATD];
__device__ float g_h1[NN * LATD];
__device__ int   g_nbr[NN * KK];

// ---------------------------------------------------------------------------
// Kernel 1: space_emb FFN  h = leaky(x@W1+b1)@W2+b2
// ---------------------------------------------------------------------------
__global__ void k_space_emb(const float* __restrict__ x,
                            const float* __restrict__ W1, const float* __restrict__ b1,
                            const float* __restrict__ W2, const float* __restrict__ b2,
                            float* __restrict__ hout) {
    __shared__ float sW1[FIN * LATD];
    __shared__ float sb1[LATD];
    __shared__ float sW2[LATD * LATD];
    __shared__ float sb2[LATD];
    int tid = threadIdx.x;
    for (int i = tid; i < FIN * LATD; i += blockDim.x) sW1[i] = W1[i];
    for (int i = tid; i < LATD; i += blockDim.x) { sb1[i] = b1[i]; sb2[i] = b2[i]; }
    {
        float4* sW24 = (float4*)sW2;
        const float4* W24 = (const float4*)W2;
#pragma unroll
        for (int i = 0; i < (LATD * LATD) / 4 / 256; ++i)
            sW24[tid + i * 256] = W24[tid + i * 256];
    }
    __syncthreads();

    int row = blockIdx.x * 64 + (tid >> 2);
    int q   = tid & 3;
    int c0  = q * 16;

    float xi0 = x[row * FIN + 0];
    float xi1 = x[row * FIN + 1];
    float xi2 = x[row * FIN + 2];
    float xi3 = x[row * FIN + 3];

    float acc[16];
#pragma unroll
    for (int c = 0; c < 16; ++c) acc[c] = sb2[c0 + c];

#pragma unroll 4
    for (int j = 0; j < LATD; ++j) {
        float tj = sb1[j]
                 + xi0 * sW1[0 * LATD + j]
                 + xi1 * sW1[1 * LATD + j]
                 + xi2 * sW1[2 * LATD + j]
                 + xi3 * sW1[3 * LATD + j];
        tj = (tj > 0.0f) ? tj : 0.01f * tj;
        const float* w2r = &sW2[j * LATD + c0];
#pragma unroll
        for (int c = 0; c < 16; ++c) acc[c] += tj * w2r[c];
    }
    float* o = &hout[row * LATD + c0];
#pragma unroll
    for (int c = 0; c < 16; ++c) o[c] = acc[c];
}

// ---------------------------------------------------------------------------
// Kernel 2: event-local kNN (k=15) on h[:, :3]. 4 blocks/event, 256 thr,
// 4 threads/query, uint8 partial lists, two lexicographic merges.
// ---------------------------------------------------------------------------
__global__ void __launch_bounds__(256, 1)
k_knn(const float* __restrict__ h,
      int* __restrict__ nbr,
      float* __restrict__ out_ei) {
    __shared__ float   px[PER], py[PER], pz[PER];
    __shared__ float   mdA[256][KK];
    __shared__ uint8_t miA[256][KK];
    __shared__ float   mdB[128][KK];
    __shared__ uint8_t miB[128][KK];

    int tid  = threadIdx.x;
    int ev   = blockIdx.x >> 2;
    int quad = blockIdx.x & 3;
    int base = ev * PER;

    {
        int n = tid;
        px[n] = h[(base + n) * LATD + 0];
        py[n] = h[(base + n) * LATD + 1];
        pz[n] = h[(base + n) * LATD + 2];
    }
    __syncthreads();

    int lq  = quad * 64 + (tid >> 2);
    int sub = tid & 3;

    float bd[KK];
    int   bi[KK];
#pragma unroll
    for (int s = 0; s < KK; ++s) { bd[s] = 3.0e38f; bi[s] = 0; }

    float xi = px[lq], yi = py[lq], zi = pz[lq];

    for (int j = sub; j < PER; j += 4) {
        float dx = __fadd_rn(xi, -px[j]);
        float dy = __fadd_rn(yi, -py[j]);
        float dz = __fadd_rn(zi, -pz[j]);
        float d  = __fadd_rn(__fadd_rn(__fmul_rn(dx, dx), __fmul_rn(dy, dy)),
                             __fmul_rn(dz, dz));
        if (j == lq) d = 3.3e38f;
        if (d < bd[KK - 1]) {
#pragma unroll
            for (int p = KK - 1; p >= 0; --p) {
                bool shift = (p > 0) && (d < bd[p - 1]);
                bool place = !shift && (d < bd[p]);
                if (shift)      { bd[p] = bd[p - 1]; bi[p] = bi[p - 1]; }
                else if (place) { bd[p] = d;         bi[p] = j;         }
            }
        }
    }
#pragma unroll
    for (int s = 0; s < KK; ++s) { mdA[tid][s] = bd[s]; miA[tid][s] = (uint8_t)bi[s]; }
    __syncthreads();

    if (tid < 128) {
        int q    = tid >> 1;
        int half = tid & 1;
        int ra = q * 4 + 2 * half, rb = ra + 1;
        int a = 0, b = 0;
#pragma unroll
        for (int s = 0; s < KK; ++s) {
            float da = mdA[ra][a], db = mdA[rb][b];
            int   ia = miA[ra][a], ib = miA[rb][b];
            bool takeA = (da < db) || (da == db && ia < ib);
            if (takeA) { mdB[tid][s] = da; miB[tid][s] = (uint8_t)ia; ++a; }
            else       { mdB[tid][s] = db; miB[tid][s] = (uint8_t)ib; ++b; }
        }
    }
    __syncthreads();

    if (tid < 64) {
        int gid = base + quad * 64 + tid;
        float fgid = (float)gid;
        int ra = 2 * tid, rb = 2 * tid + 1;
        int a = 0, b = 0;
#pragma unroll
        for (int s = 0; s < KK; ++s) {
            float da = mdB[ra][a], db = mdB[rb][b];
            int   ia = miB[ra][a], ib = miB[rb][b];
            bool takeA = (da < db) || (da == db && ia < ib);
            int  pick  = takeA ? ia : ib;
            if (takeA) ++a; else ++b;
            int gj = base + pick;
            int e  = gid * KK + s;
            nbr[e] = gj;
            out_ei[e]       = (float)gj;
            out_ei[NKE + e] = fgid;
        }
    }
}

// ---------------------------------------------------------------------------
// Kernel 3: GIN layer. 256 threads, 32 rows/block, grid 256, occupancy 2.
// Fat 8-row tiles (4 row-groups) cut weight-read redundancy; row-pairs are
// packed into f32x2 lanes and accumulated with FFMA2 (fma.rn.f32x2).
// ---------------------------------------------------------------------------
#define M_S  64    // m / sh row stride
#define ST_S 136   // st / su row stride (16B-aligned, 2-way-conflict-free)

template <bool FUSE_OE>
__global__ void __launch_bounds__(256, 2)
k_gin(const float* __restrict__ h_in,
      float* __restrict__ h_out,
      const int* __restrict__ nbr,
      const float* __restrict__ Wa, const float* __restrict__ ba,
      const float* __restrict__ Wb, const float* __restrict__ bb,
      const float* __restrict__ W1o, const float* __restrict__ b1o,
      const float* __restrict__ W2o, const float* __restrict__ b2o,
      float* __restrict__ xe) {
    extern __shared__ float sm[];
    float* sWa  = sm;                    // 8192
    float* sWb  = sWa + 8192;            // 8192
    float* sba  = sWb + 8192;            // 128
    float* sbb  = sba + 128;             // 64
    float* m    = sbb + 64;              // 32*M_S = 2048 (reused as sh for OE)
    float* st   = m + 32 * M_S;          // 32*ST_S = 4352 (reused as su)
    float* sW1o = st + 32 * ST_S;        // 4096 (FUSE_OE)
    float* sW2o = sW1o + 4096;           // 256
    float* sb1o = sW2o + 256;            // 64
    float* sb2o = sb1o + 64;             // 4

    int tid = threadIdx.x;
    // ---- stage weights ------------------------------------------------------
    {
        const float4* Wa4 = (const float4*)Wa;
        const float4* Wb4 = (const float4*)Wb;
        float4* dA = (float4*)sWa;
        float4* dB = (float4*)sWb;
#pragma unroll
        for (int i = 0; i < 8; ++i) {
            dA[tid + i * 256] = Wa4[tid + i * 256];
            dB[tid + i * 256] = Wb4[tid + i * 256];
        }
        if (tid < 128) sba[tid] = ba[tid];
        if (tid < 64)  sbb[tid] = bb[tid];
        if (FUSE_OE) {
            const float4* W1o4 = (const float4*)W1o;
            float4* d3 = (float4*)sW1o;
#pragma unroll
            for (int i = 0; i < 4; ++i) d3[tid + i * 256] = W1o4[tid + i * 256];
            sW2o[tid] = W2o[tid];
            if (tid < 64) sb1o[tid] = b1o[tid];
            if (tid < 4)  sb2o[tid] = b2o[tid];
        }
    }

    int base = blockIdx.x * 32;

    // ---- Gather: m = h_i + sum of 15 neighbors (row-major) -----------------
    {
        int r   = tid >> 3;              // 0..31
        int oct = tid & 7;
        int i   = base + r;
        const float4* h4 = (const float4*)h_in;
        const int* nb = &nbr[i * KK];
        float4 a0 = h4[i * 16 + oct * 2];
        float4 a1 = h4[i * 16 + oct * 2 + 1];
#pragma unroll
        for (int s = 0; s < KK; ++s) {
            int j = nb[s];
            float4 v0 = h4[j * 16 + oct * 2];
            float4 v1 = h4[j * 16 + oct * 2 + 1];
            a0.x += v0.x; a0.y += v0.y; a0.z += v0.z; a0.w += v0.w;
            a1.x += v1.x; a1.y += v1.y; a1.z += v1.z; a1.w += v1.w;
        }
        *(float4*)&m[r * M_S + oct * 8]     = a0;
        *(float4*)&m[r * M_S + oct * 8 + 4] = a1;
    }
    __syncthreads();

    int rg = tid >> 6;                  // 0..3 row-group
    int ct = tid & 63;
    int r0 = rg * 8;

    // ---- Phase B: t = relu(m @ Wa + ba). tile 8 rows x 2 cols, FFMA2 -------
    {
        int c1 = ct * 2;
        ull acc[4][2];
        {
            float bl = sba[c1], bh = sba[c1 + 1];
#pragma unroll
            for (int p = 0; p < 4; ++p) { acc[p][0] = pk2(bl, bl); acc[p][1] = pk2(bh, bh); }
        }
#pragma unroll
        for (int k = 0; k < 64; k += 4) {
            float av[8][4];
#pragma unroll
            for (int rr = 0; rr < 8; ++rr) {
                float4 t = *(const float4*)&m[(r0 + rr) * M_S + k];   // broadcast
                av[rr][0] = t.x; av[rr][1] = t.y; av[rr][2] = t.z; av[rr][3] = t.w;
            }
            float2 bw[4];
#pragma unroll
            for (int kk = 0; kk < 4; ++kk)
                bw[kk] = *(const float2*)&sWa[(k + kk) * HIDD + c1];
#pragma unroll
            for (int kk = 0; kk < 4; ++kk) {
                ull bx = pk2(bw[kk].x, bw[kk].x);
                ull by = pk2(bw[kk].y, bw[kk].y);
#pragma unroll
                for (int p = 0; p < 4; ++p) {
                    ull ap = pk2(av[2 * p][kk], av[2 * p + 1][kk]);
                    acc[p][0] = f2fma(ap, bx, acc[p][0]);
                    acc[p][1] = f2fma(ap, by, acc[p][1]);
                }
            }
        }
#pragma unroll
        for (int p = 0; p < 4; ++p) {
            float lo, hi;
            upk2(lo, hi, acc[p][0]);
            st[(r0 + 2 * p) * ST_S + c1]     = fmaxf(lo, 0.f);
            st[(r0 + 2 * p + 1) * ST_S + c1] = fmaxf(hi, 0.f);
            upk2(lo, hi, acc[p][1]);
            st[(r0 + 2 * p) * ST_S + c1 + 1]     = fmaxf(lo, 0.f);
            st[(r0 + 2 * p + 1) * ST_S + c1 + 1] = fmaxf(hi, 0.f);
        }
    }
    __syncthreads();

    // ---- Phase C: h_out = h_in + t @ Wb + bb. tile 8 rows x 1 col, FFMA2 ---
    int c = ct;
    {
        ull acc2[4];
        {
            float bv = sbb[c];
#pragma unroll
            for (int p = 0; p < 4; ++p) acc2[p] = pk2(bv, bv);
        }
#pragma unroll 8
        for (int k = 0; k < 128; k += 4) {
            float av[8][4];
#pragma unroll
            for (int rr = 0; rr < 8; ++rr) {
                float4 t = *(const float4*)&st[(r0 + rr) * ST_S + k];  // broadcast
                av[rr][0] = t.x; av[rr][1] = t.y; av[rr][2] = t.z; av[rr][3] = t.w;
            }
            float bw[4];
#pragma unroll
            for (int kk = 0; kk < 4; ++kk) bw[kk] = sWb[(k + kk) * LATD + c];
#pragma unroll
            for (int kk = 0; kk < 4; ++kk) {
                ull bd = pk2(bw[kk], bw[kk]);
#pragma unroll
                for (int p = 0; p < 4; ++p) {
                    ull ap = pk2(av[2 * p][kk], av[2 * p + 1][kk]);
                    acc2[p] = f2fma(ap, bd, acc2[p]);
                }
            }
        }
#pragma unroll
        for (int p = 0; p < 4; ++p) {
            float lo, hi;
            upk2(lo, hi, acc2[p]);
            int rl = r0 + 2 * p, rh = rl + 1;
            float olo = h_in[(base + rl) * LATD + c] + lo;
            float ohi = h_in[(base + rh) * LATD + c] + hi;
            h_out[(base + rl) * LATD + c] = olo;
            h_out[(base + rh) * LATD + c] = ohi;
            if (FUSE_OE) { m[rl * M_S + c] = olo; m[rh * M_S + c] = ohi; }
        }
    }

    if (FUSE_OE) {
        __syncthreads();
        // ---- OE1: u = leaky(h @ W1o + b1o). tile 8 rows x 1 col, FFMA2 -----
        ull u[4];
        {
            float bv = sb1o[c];
#pragma unroll
            for (int p = 0; p < 4; ++p) u[p] = pk2(bv, bv);
        }
#pragma unroll 8
        for (int k = 0; k < 64; k += 4) {
            float av[8][4];
#pragma unroll
            for (int rr = 0; rr < 8; ++rr) {
                float4 t = *(const float4*)&m[(r0 + rr) * M_S + k];   // broadcast
                av[rr][0] = t.x; av[rr][1] = t.y; av[rr][2] = t.z; av[rr][3] = t.w;
            }
            float bw[4];
#pragma unroll
            for (int kk = 0; kk < 4; ++kk) bw[kk] = sW1o[(k + kk) * LATD + c];
#pragma unroll
            for (int kk = 0; kk < 4; ++kk) {
                ull bd = pk2(bw[kk], bw[kk]);
#pragma unroll
                for (int p = 0; p < 4; ++p) {
                    ull ap = pk2(av[2 * p][kk], av[2 * p + 1][kk]);
                    u[p] = f2fma(ap, bd, u[p]);
                }
            }
        }
#pragma unroll
        for (int p = 0; p < 4; ++p) {
            float lo, hi;
            upk2(lo, hi, u[p]);
            lo = (lo > 0.f) ? lo : 0.01f * lo;
            hi = (hi > 0.f) ? hi : 0.01f * hi;
            st[(r0 + 2 * p) * ST_S + c]     = lo;
            st[(r0 + 2 * p + 1) * ST_S + c] = hi;
        }
        __syncthreads();
        // ---- OE2: x_emb = u @ W2o + b2o; 128 threads = (row, feature) ------
        if (tid < 128) {
            int row = tid >> 2;
            int oc  = tid & 3;
            float a = sb2o[oc];
#pragma unroll 8
            for (int k = 0; k < LATD; ++k)
                a += st[row * ST_S + k] * sW2o[k * FOUT + oc];
            xe[(base + row) * FOUT + oc] = a;
        }
    }
}

// ---------------------------------------------------------------------------
extern "C" void kernel_launch(void* const* d_in, const int* in_sizes, int n_in,
                              void* d_out, int out_size) {
    const float* x     = (const float*)d_in[0];
    const float* W_se1 = (const float*)d_in[3];
    const float* b_se1 = (const float*)d_in[4];
    const float* W_se2 = (const float*)d_in[5];
    const float* b_se2 = (const float*)d_in[6];
    const float* W_g1a = (const float*)d_in[7];
    const float* b_g1a = (const float*)d_in[8];
    const float* W_g1b = (const float*)d_in[9];
    const float* b_g1b = (const float*)d_in[10];
    const float* W_g2a = (const float*)d_in[11];
    const float* b_g2a = (const float*)d_in[12];
    const float* W_g2b = (const float*)d_in[13];
    const float* b_g2b = (const float*)d_in[14];
    const float* W_oe1 = (const float*)d_in[15];
    const float* b_oe1 = (const float*)d_in[16];
    const float* W_oe2 = (const float*)d_in[17];
    const float* b_oe2 = (const float*)d_in[18];

    float* out    = (float*)d_out;
    float* out_h  = out;
    float* out_xe = out + XE_OFF;
    float* out_ei = out + EI_OFF;

    void *p_h0, *p_h1, *p_nbr;
    cudaGetSymbolAddress(&p_h0, g_h0);
    cudaGetSymbolAddress(&p_h1, g_h1);
    cudaGetSymbolAddress(&p_nbr, g_nbr);
    float* h0 = (float*)p_h0;
    float* h1 = (float*)p_h1;
    int*   nb = (int*)p_nbr;

    static const size_t gin_smem_base =
        (size_t)(8192 + 8192 + 128 + 64 + 32 * M_S + 32 * ST_S) * sizeof(float);
    static const size_t gin_smem_oe = gin_smem_base +
        (size_t)(4096 + 256 + 64 + 4) * sizeof(float);
    cudaFuncSetAttribute(k_gin<false>, cudaFuncAttributeMaxDynamicSharedMemorySize,
                         (int)gin_smem_base);
    cudaFuncSetAttribute(k_gin<true>, cudaFuncAttributeMaxDynamicSharedMemorySize,
                         (int)gin_smem_oe);

    // 1) space_emb -> h0
    k_space_emb<<<NN / 64, 256>>>(x, W_se1, b_se1, W_se2, b_se2, h0);
    // 2) kNN on h0[:, :3] -> nbr, ei written to output
    k_knn<<<GEV * 4, 256>>>(h0, nb, out_ei);
    // 3) GIN layer 1: h0 -> h1
    k_gin<false><<<NN / 32, 256, gin_smem_base>>>(h0, h1, nb,
        W_g1a, b_g1a, W_g1b, b_g1b, nullptr, nullptr, nullptr, nullptr, nullptr);
    // 4) GIN layer 2 + fused out_emb: h1 -> d_out (h), x_emb -> d_out
    k_gin<true><<<NN / 32, 256, gin_smem_oe>>>(h1, out_h, nb,
        W_g2a, b_g2a, W_g2b, b_g2b, W_oe1, b_oe1, W_oe2, b_oe2, out_xe);
}

// round 11
// speedup vs baseline: 1.1248x; 1.0880x over previous
#include <cuda_runtime.h>
#include <cuda_bf16.h>
#include <stdint.h>

// Problem constants
#define NN      8192
#define GEV     32
#define PER     256      // nodes per event
#define KK      15
#define FIN     4
#define FOUT    4
#define LATD    64
#define HIDD    128

#define H_ELEMS   (NN * LATD)          // 524288
#define XE_ELEMS  (NN * FOUT)          // 32768
#define NKE       (NN * KK)            // 122880
#define XE_OFF    (H_ELEMS)
#define EI_OFF    (H_ELEMS + XE_ELEMS) // 557056

#define FULLMASK 0xffffffffu

// Device scratch (no allocations allowed)
__device__ float g_h0[NN * LATD];
__device__ float g_h1[NN * LATD];
__device__ int   g_nbr[NN * KK];

// ---------------------------------------------------------------------------
// Kernel 1: fused space_emb + event-local kNN.
// grid 128 = one CTA per 64-query quad (4 CTAs/event), 256 threads.
//  part 1: full space_emb for the CTA's own 64 rows -> h0 (4 thr/row).
//  part 2: positions (first 3 emb cols) for ALL 256 event rows, recomputed
//          redundantly (1 thr/row) -> smem. Identical across the event's CTAs.
//  part 3: kNN scan, 4 threads/query, sorted top-15, two lexicographic
//          (d, idx) merges — matches lax.top_k tie-breaking.
// smem union: the W2 staging region is reused for the merge arrays.
// ---------------------------------------------------------------------------
#define SE_W1   0            // 256 f
#define SE_B1   256          // 64 f
#define SE_B2   320          // 64 f
#define SE_U    384          // union: sW2 [4096 f] | mdA[256*15 f] + miA[3840 B]
#define SE_PX   5184         // 256 f
#define SE_PY   5440         // 256 f
#define SE_PZ   5696         // 256 f
#define SE_MDB  5952         // 128*15 f
#define SE_MIB  7872         // 1920 B = 480 f
#define SE_TOT  8352         // floats

__global__ void __launch_bounds__(256, 1)
k_se_knn(const float* __restrict__ x,
         const float* __restrict__ W1, const float* __restrict__ b1,
         const float* __restrict__ W2, const float* __restrict__ b2,
         float* __restrict__ hout,
         int* __restrict__ nbr,
         float* __restrict__ out_ei) {
    extern __shared__ float sm[];
    float* sW1 = sm + SE_W1;
    float* sb1 = sm + SE_B1;
    float* sb2 = sm + SE_B2;
    float* sW2 = sm + SE_U;
    float* px  = sm + SE_PX;
    float* py  = sm + SE_PY;
    float* pz  = sm + SE_PZ;
    float*   mdA = sm + SE_U;                       // after FFN: reuse
    uint8_t* miA = (uint8_t*)(sm + SE_U + 3840);
    float*   mdB = sm + SE_MDB;
    uint8_t* miB = (uint8_t*)(sm + SE_MIB);

    int tid  = threadIdx.x;
    int ev   = blockIdx.x >> 2;
    int quad = blockIdx.x & 3;
    int base = ev * PER;

    // ---- stage weights (all branches unconditional — BUGFIX vs R10) --------
    if (tid < FIN * LATD) sW1[tid] = W1[tid];       // 256 floats
    if (tid < 64) sb1[tid] = b1[tid];               // was dead code in R10
    if (tid < 64) sb2[tid] = b2[tid];
    {
        float4* d = (float4*)sW2;
        const float4* s = (const float4*)W2;
#pragma unroll
        for (int i = 0; i < 4; ++i) d[tid + i * 256] = s[tid + i * 256];
    }
    __syncthreads();

    // ---- part 1: space_emb for own 64 rows (4 threads/row, 16 cols each) ---
    {
        int lrow = quad * 64 + (tid >> 2);   // event-local row
        int row  = base + lrow;
        int q    = tid & 3;
        int c0   = q * 16;

        float4 xi = *(const float4*)&x[row * FIN];

        float acc[16];
#pragma unroll
        for (int c = 0; c < 16; ++c) acc[c] = sb2[c0 + c];

#pragma unroll 4
        for (int j = 0; j < LATD; ++j) {
            float tj = sb1[j]
                     + xi.x * sW1[0 * LATD + j]
                     + xi.y * sW1[1 * LATD + j]
                     + xi.z * sW1[2 * LATD + j]
                     + xi.w * sW1[3 * LATD + j];
            tj = (tj > 0.0f) ? tj : 0.01f * tj;
            const float* w2r = &sW2[j * LATD + c0];
#pragma unroll
            for (int c = 0; c < 16; ++c) acc[c] += tj * w2r[c];
        }
        float* o = &hout[row * LATD + c0];
#pragma unroll
        for (int c = 0; c < 16; ++c) o[c] = acc[c];
    }

    // ---- part 2: positions for all 256 event rows (1 thread/row) -----------
    {
        int n   = tid;
        int row = base + n;
        float4 xi = *(const float4*)&x[row * FIN];
        float ax = 0.f, ay = 0.f, az = 0.f;
#pragma unroll 4
        for (int j = 0; j < LATD; ++j) {
            float tj = sb1[j]
                     + xi.x * sW1[0 * LATD + j]
                     + xi.y * sW1[1 * LATD + j]
                     + xi.z * sW1[2 * LATD + j]
                     + xi.w * sW1[3 * LATD + j];
            tj = (tj > 0.0f) ? tj : 0.01f * tj;
            const float* w2r = &sW2[j * LATD];
            ax += tj * w2r[0];
            ay += tj * w2r[1];
            az += tj * w2r[2];
        }
        px[n] = ax + sb2[0];
        py[n] = ay + sb2[1];
        pz[n] = az + sb2[2];
    }
    __syncthreads();   // positions ready; sW2 no longer needed

    // ---- part 3: kNN scan, 4 threads/query ---------------------------------
    {
        int lq  = quad * 64 + (tid >> 2);
        int sub = tid & 3;

        float bd[KK];
        int   bi[KK];
#pragma unroll
        for (int s = 0; s < KK; ++s) { bd[s] = 3.0e38f; bi[s] = 0; }

        float xi = px[lq], yi = py[lq], zi = pz[lq];

        for (int j = sub; j < PER; j += 4) {
            float dx = __fadd_rn(xi, -px[j]);
            float dy = __fadd_rn(yi, -py[j]);
            float dz = __fadd_rn(zi, -pz[j]);
            float d  = __fadd_rn(__fadd_rn(__fmul_rn(dx, dx), __fmul_rn(dy, dy)),
                                 __fmul_rn(dz, dz));
            if (j == lq) d = 3.3e38f;            // exclude self
            if (d < bd[KK - 1]) {
#pragma unroll
                for (int p = KK - 1; p >= 0; --p) {
                    bool shift = (p > 0) && (d < bd[p - 1]);
                    bool place = !shift && (d < bd[p]);
                    if (shift)      { bd[p] = bd[p - 1]; bi[p] = bi[p - 1]; }
                    else if (place) { bd[p] = d;         bi[p] = j;         }
                }
            }
        }
#pragma unroll
        for (int s = 0; s < KK; ++s) {
            mdA[tid * KK + s] = bd[s];
            miA[tid * KK + s] = (uint8_t)bi[s];
        }
    }
    __syncthreads();

    // merge round 1: 128 threads, pairwise (sub 0,1) and (sub 2,3)
    if (tid < 128) {
        int q    = tid >> 1;
        int half = tid & 1;
        int ra = q * 4 + 2 * half, rb = ra + 1;
        int a = 0, b = 0;
#pragma unroll
        for (int s = 0; s < KK; ++s) {
            float da = mdA[ra * KK + a], db = mdA[rb * KK + b];
            int   ia = miA[ra * KK + a], ib = miA[rb * KK + b];
            bool takeA = (da < db) || (da == db && ia < ib);
            if (takeA) { mdB[tid * KK + s] = da; miB[tid * KK + s] = (uint8_t)ia; ++a; }
            else       { mdB[tid * KK + s] = db; miB[tid * KK + s] = (uint8_t)ib; ++b; }
        }
    }
    __syncthreads();

    // merge round 2: 64 threads, final output
    if (tid < 64) {
        int gid = base + quad * 64 + tid;
        float fgid = (float)gid;
        int ra = 2 * tid, rb = 2 * tid + 1;
        int a = 0, b = 0;
#pragma unroll
        for (int s = 0; s < KK; ++s) {
            float da = mdB[ra * KK + a], db = mdB[rb * KK + b];
            int   ia = miB[ra * KK + a], ib = miB[rb * KK + b];
            bool takeA = (da < db) || (da == db && ia < ib);
            int  pick  = takeA ? ia : ib;
            if (takeA) ++a; else ++b;
            int gj = base + pick;
            int e  = gid * KK + s;
            nbr[e] = gj;
            out_ei[e]       = (float)gj;
            out_ei[NKE + e] = fgid;
        }
    }
}

// ---------------------------------------------------------------------------
// Kernel 2: GIN layer (R7 best config). 256 threads, 32 rows/block, grid 256,
// occupancy 2. Phase B 4x4 tile (a = warp broadcast from transposed mT),
// phase C / OE 4x2 tiles. FUSE_OE epilogue reuses mT (sh) and st (su).
// ---------------------------------------------------------------------------
#define MT_S 36    // mT row stride (k-major, 32 rows + pad)
#define ST_S 132   // st row stride (128 + pad)
#define SH_S 68    // sh row stride (64 + pad), aliased onto mT

template <bool FUSE_OE>
__global__ void __launch_bounds__(256, 2)
k_gin(const float* __restrict__ h_in,
      float* __restrict__ h_out,
      const int* __restrict__ nbr,
      const float* __restrict__ Wa, const float* __restrict__ ba,
      const float* __restrict__ Wb, const float* __restrict__ bb,
      const float* __restrict__ W1o, const float* __restrict__ b1o,
      const float* __restrict__ W2o, const float* __restrict__ b2o,
      float* __restrict__ xe) {
    extern __shared__ float sm[];
    float* sWa  = sm;                    // 8192
    float* sWb  = sWa + 8192;            // 8192
    float* sba  = sWb + 8192;            // 128
    float* sbb  = sba + 128;             // 64
    float* mT   = sbb + 64;              // 64*MT_S = 2304 (reused as sh 32*SH_S)
    float* st   = mT + 64 * MT_S;        // 32*ST_S = 4224 (reused as su)
    float* sW1o = st + 32 * ST_S;        // 4096 (FUSE_OE)
    float* sW2o = sW1o + 4096;           // 256
    float* sb1o = sW2o + 256;            // 64
    float* sb2o = sb1o + 64;             // 4

    int tid = threadIdx.x;
    // ---- stage weights (row-major, vectorized) -----------------------------
    {
        const float4* Wa4 = (const float4*)Wa;
        const float4* Wb4 = (const float4*)Wb;
        float4* dA = (float4*)sWa;
        float4* dB = (float4*)sWb;
#pragma unroll
        for (int i = 0; i < 8; ++i) {
            dA[tid + i * 256] = Wa4[tid + i * 256];
            dB[tid + i * 256] = Wb4[tid + i * 256];
        }
        if (tid < 128) sba[tid] = ba[tid];
        if (tid < 64)  sbb[tid] = bb[tid];
        if (FUSE_OE) {
            const float4* W1o4 = (const float4*)W1o;
            float4* d3 = (float4*)sW1o;
#pragma unroll
            for (int i = 0; i < 4; ++i) d3[tid + i * 256] = W1o4[tid + i * 256];
            sW2o[tid] = W2o[tid];        // 256 floats exactly
            if (tid < 64) sb1o[tid] = b1o[tid];
            if (tid < 4)  sb2o[tid] = b2o[tid];
        }
    }

    int base = blockIdx.x * 32;

    // ---- Gather: m = h_i + sum of 15 neighbors -> mT[k][row] ---------------
    {
        int r   = tid >> 3;              // 0..31
        int oct = tid & 7;
        int i   = base + r;
        const float4* h4 = (const float4*)h_in;
        const int* nb = &nbr[i * KK];
        float4 a0 = h4[i * 16 + oct * 2];
        float4 a1 = h4[i * 16 + oct * 2 + 1];
#pragma unroll
        for (int s = 0; s < KK; ++s) {
            int j = nb[s];
            float4 v0 = h4[j * 16 + oct * 2];
            float4 v1 = h4[j * 16 + oct * 2 + 1];
            a0.x += v0.x; a0.y += v0.y; a0.z += v0.z; a0.w += v0.w;
            a1.x += v1.x; a1.y += v1.y; a1.z += v1.z; a1.w += v1.w;
        }
        int k0 = oct * 8;
        mT[(k0 + 0) * MT_S + r] = a0.x;
        mT[(k0 + 1) * MT_S + r] = a0.y;
        mT[(k0 + 2) * MT_S + r] = a0.z;
        mT[(k0 + 3) * MT_S + r] = a0.w;
        mT[(k0 + 4) * MT_S + r] = a1.x;
        mT[(k0 + 5) * MT_S + r] = a1.y;
        mT[(k0 + 6) * MT_S + r] = a1.z;
        mT[(k0 + 7) * MT_S + r] = a1.w;
    }
    __syncthreads();

    int r0 = (tid >> 5) * 4;            // warp-uniform row base (0..28)
    int cx = tid & 31;

    // ---- Phase B: t = relu(m @ Wa + ba), thread tile 4x4 -------------------
    {
        int c0 = cx * 4;
        float acc[4][4];
#pragma unroll
        for (int i = 0; i < 4; ++i)
#pragma unroll
            for (int c = 0; c < 4; ++c) acc[i][c] = sba[c0 + c];

#pragma unroll 8
        for (int k = 0; k < 64; ++k) {
            float4 a = *(const float4*)&mT[k * MT_S + r0];     // warp broadcast
            float4 b = *(const float4*)&sWa[k * HIDD + c0];
            acc[0][0] += a.x * b.x; acc[0][1] += a.x * b.y;
            acc[0][2] += a.x * b.z; acc[0][3] += a.x * b.w;
            acc[1][0] += a.y * b.x; acc[1][1] += a.y * b.y;
            acc[1][2] += a.y * b.z; acc[1][3] += a.y * b.w;
            acc[2][0] += a.z * b.x; acc[2][1] += a.z * b.y;
            acc[2][2] += a.z * b.z; acc[2][3] += a.z * b.w;
            acc[3][0] += a.w * b.x; acc[3][1] += a.w * b.y;
            acc[3][2] += a.w * b.z; acc[3][3] += a.w * b.w;
        }
#pragma unroll
        for (int i = 0; i < 4; ++i) {
            float4 q;
            q.x = fmaxf(acc[i][0], 0.f);
            q.y = fmaxf(acc[i][1], 0.f);
            q.z = fmaxf(acc[i][2], 0.f);
            q.w = fmaxf(acc[i][3], 0.f);
            *(float4*)&st[(r0 + i) * ST_S + c0] = q;
        }
    }
    __syncthreads();

    // ---- Phase C: h_out = h_in + t @ Wb + bb, thread tile 4x2 --------------
    int c1 = cx * 2;
    {
        float acc2[4][2];
#pragma unroll
        for (int i = 0; i < 4; ++i) { acc2[i][0] = sbb[c1]; acc2[i][1] = sbb[c1 + 1]; }

#pragma unroll 4
        for (int k2 = 0; k2 < HIDD; k2 += 4) {
            float4 ar[4];
            float2 bk[4];
#pragma unroll
            for (int i = 0; i < 4; ++i) ar[i] = *(const float4*)&st[(r0 + i) * ST_S + k2];
#pragma unroll
            for (int j = 0; j < 4; ++j) bk[j] = *(const float2*)&sWb[(k2 + j) * LATD + c1];
#pragma unroll
            for (int i = 0; i < 4; ++i) {
                acc2[i][0] += ar[i].x * bk[0].x + ar[i].y * bk[1].x
                            + ar[i].z * bk[2].x + ar[i].w * bk[3].x;
                acc2[i][1] += ar[i].x * bk[0].y + ar[i].y * bk[1].y
                            + ar[i].z * bk[2].y + ar[i].w * bk[3].y;
            }
        }
#pragma unroll
        for (int i = 0; i < 4; ++i) {
            float2 hv = *(const float2*)&h_in[(base + r0 + i) * LATD + c1];
            float2 o;
            o.x = hv.x + acc2[i][0];
            o.y = hv.y + acc2[i][1];
            *(float2*)&h_out[(base + r0 + i) * LATD + c1] = o;
            if (FUSE_OE) *(float2*)&mT[(r0 + i) * SH_S + c1] = o;  // sh = mT reuse
        }
    }

    if (FUSE_OE) {
        __syncthreads();
        // ---- OE1: u = leaky(h @ W1o + b1o), thread tile 4x2 (sh=mT) --------
        float u[4][2];
#pragma unroll
        for (int i = 0; i < 4; ++i) { u[i][0] = sb1o[c1]; u[i][1] = sb1o[c1 + 1]; }
#pragma unroll 4
        for (int k = 0; k < LATD; k += 4) {
            float4 ar[4];
            float2 bk[4];
#pragma unroll
            for (int i = 0; i < 4; ++i) ar[i] = *(const float4*)&mT[(r0 + i) * SH_S + k];
#pragma unroll
            for (int j = 0; j < 4; ++j) bk[j] = *(const float2*)&sW1o[(k + j) * LATD + c1];
#pragma unroll
            for (int i = 0; i < 4; ++i) {
                u[i][0] += ar[i].x * bk[0].x + ar[i].y * bk[1].x
                         + ar[i].z * bk[2].x + ar[i].w * bk[3].x;
                u[i][1] += ar[i].x * bk[0].y + ar[i].y * bk[1].y
                         + ar[i].z * bk[2].y + ar[i].w * bk[3].y;
            }
        }
#pragma unroll
        for (int i = 0; i < 4; ++i) {
            float2 q;
            q.x = (u[i][0] > 0.f) ? u[i][0] : 0.01f * u[i][0];
            q.y = (u[i][1] > 0.f) ? u[i][1] : 0.01f * u[i][1];
            *(float2*)&st[(r0 + i) * ST_S + c1] = q;   // su = st reuse
        }
        __syncthreads();
        // ---- OE2: x_emb = u @ W2o + b2o; 128 threads = (row, feature) ------
        if (tid < 128) {
            int row = tid >> 2;
            int oc  = tid & 3;
            float a = sb2o[oc];
#pragma unroll 8
            for (int k = 0; k < LATD; ++k)
                a += st[row * ST_S + k] * sW2o[k * FOUT + oc];
            xe[(base + row) * FOUT + oc] = a;
        }
    }
}

// ---------------------------------------------------------------------------
extern "C" void kernel_launch(void* const* d_in, const int* in_sizes, int n_in,
                              void* d_out, int out_size) {
    const float* x     = (const float*)d_in[0];
    const float* W_se1 = (const float*)d_in[3];
    const float* b_se1 = (const float*)d_in[4];
    const float* W_se2 = (const float*)d_in[5];
    const float* b_se2 = (const float*)d_in[6];
    const float* W_g1a = (const float*)d_in[7];
    const float* b_g1a = (const float*)d_in[8];
    const float* W_g1b = (const float*)d_in[9];
    const float* b_g1b = (const float*)d_in[10];
    const float* W_g2a = (const float*)d_in[11];
    const float* b_g2a = (const float*)d_in[12];
    const float* W_g2b = (const float*)d_in[13];
    const float* b_g2b = (const float*)d_in[14];
    const float* W_oe1 = (const float*)d_in[15];
    const float* b_oe1 = (const float*)d_in[16];
    const float* W_oe2 = (const float*)d_in[17];
    const float* b_oe2 = (const float*)d_in[18];

    float* out    = (float*)d_out;
    float* out_h  = out;
    float* out_xe = out + XE_OFF;
    float* out_ei = out + EI_OFF;

    void *p_h0, *p_h1, *p_nbr;
    cudaGetSymbolAddress(&p_h0, g_h0);
    cudaGetSymbolAddress(&p_h1, g_h1);
    cudaGetSymbolAddress(&p_nbr, g_nbr);
    float* h0 = (float*)p_h0;
    float* h1 = (float*)p_h1;
    int*   nb = (int*)p_nbr;

    static const size_t se_smem = (size_t)SE_TOT * sizeof(float);
    static const size_t gin_smem_base =
        (size_t)(8192 + 8192 + 128 + 64 + 64 * MT_S + 32 * ST_S) * sizeof(float);
    static const size_t gin_smem_oe = gin_smem_base +
        (size_t)(4096 + 256 + 64 + 4) * sizeof(float);
    cudaFuncSetAttribute(k_gin<false>, cudaFuncAttributeMaxDynamicSharedMemorySize,
                         (int)gin_smem_base);
    cudaFuncSetAttribute(k_gin<true>, cudaFuncAttributeMaxDynamicSharedMemorySize,
                         (int)gin_smem_oe);

    // 1) fused space_emb + kNN -> h0, nbr, ei
    k_se_knn<<<GEV * 4, 256, se_smem>>>(x, W_se1, b_se1, W_se2, b_se2,
                                        h0, nb, out_ei);
    // 2) GIN layer 1: h0 -> h1
    k_gin<false><<<NN / 32, 256, gin_smem_base>>>(h0, h1, nb,
        W_g1a, b_g1a, W_g1b, b_g1b, nullptr, nullptr, nullptr, nullptr, nullptr);
    // 3) GIN layer 2 + fused out_emb: h1 -> d_out (h), x_emb -> d_out
    k_gin<true><<<NN / 32, 256, gin_smem_oe>>>(h1, out_h, nb,
        W_g2a, b_g2a, W_g2b, b_g2b, W_oe1, b_oe1, W_oe2, b_oe2, out_xe);
}

// round 12
// speedup vs baseline: 1.1260x; 1.0010x over previous
#include <cuda_runtime.h>
#include <cuda_bf16.h>
#include <stdint.h>

// Problem constants
#define NN      8192
#define GEV     32
#define PER     256      // nodes per event
#define KK      15
#define FIN     4
#define FOUT    4
#define LATD    64
#define HIDD    128

#define H_ELEMS   (NN * LATD)          // 524288
#define XE_ELEMS  (NN * FOUT)          // 32768
#define NKE       (NN * KK)            // 122880
#define XE_OFF    (H_ELEMS)
#define EI_OFF    (H_ELEMS + XE_ELEMS) // 557056

#define FULLMASK 0xffffffffu

// Device scratch (no allocations allowed)
__device__ float g_h0[NN * LATD];
__device__ float g_h1[NN * LATD];
__device__ int   g_nbr[NN * KK];

// ---------------------------------------------------------------------------
// Kernel 1: fused space_emb + event-local kNN.
// grid 256 = one CTA per 32-query octant (8 CTAs/event), 256 threads, occ 2.
//  part 1: space_emb for the CTA's own 32 rows -> h0 (8 thr/row, 8 cols each).
//  part 2: positions (first 3 emb cols) for ALL 256 event rows (1 thr/row).
//  part 3: kNN scan, 8 threads/query (32 candidates each), sorted top-15,
//          three lexicographic (d, idx) merge rounds — matches lax.top_k.
// smem union: the W2 staging region is reused for the merge arrays.
// ---------------------------------------------------------------------------
#define SE_W1   0            // 256 f
#define SE_B1   256          // 64 f
#define SE_B2   320          // 64 f
#define SE_U    384          // union: sW2 [4096 f] | mdA[256*15 f]+miA[3840 B]
#define SE_PX   5184         // 256 f
#define SE_PY   5440         // 256 f
#define SE_PZ   5696         // 256 f
#define SE_MDB  5952         // 128*15 f
#define SE_MIB  7872         // 1920 B = 480 f
#define SE_TOT  8352         // floats

__global__ void __launch_bounds__(256, 2)
k_se_knn(const float* __restrict__ x,
         const float* __restrict__ W1, const float* __restrict__ b1,
         const float* __restrict__ W2, const float* __restrict__ b2,
         float* __restrict__ hout,
         int* __restrict__ nbr,
         float* __restrict__ out_ei) {
    extern __shared__ float sm[];
    float* sW1 = sm + SE_W1;
    float* sb1 = sm + SE_B1;
    float* sb2 = sm + SE_B2;
    float* sW2 = sm + SE_U;
    float* px  = sm + SE_PX;
    float* py  = sm + SE_PY;
    float* pz  = sm + SE_PZ;
    float*   mdA = sm + SE_U;                       // after FFN: reuse
    uint8_t* miA = (uint8_t*)(sm + SE_U + 3840);
    float*   mdB = sm + SE_MDB;
    uint8_t* miB = (uint8_t*)(sm + SE_MIB);
    float*   mdC = mdA;                             // round-2 output (64*15 f)
    uint8_t* miC = miA;

    int tid  = threadIdx.x;
    int ev   = blockIdx.x >> 3;
    int oct  = blockIdx.x & 7;
    int base = ev * PER;

    // ---- stage weights ------------------------------------------------------
    if (tid < FIN * LATD) sW1[tid] = W1[tid];       // 256 floats
    if (tid < 64) sb1[tid] = b1[tid];
    if (tid < 64) sb2[tid] = b2[tid];
    {
        float4* d = (float4*)sW2;
        const float4* s = (const float4*)W2;
#pragma unroll
        for (int i = 0; i < 4; ++i) d[tid + i * 256] = s[tid + i * 256];
    }
    __syncthreads();

    // ---- part 1: space_emb for own 32 rows (8 threads/row, 8 cols each) ----
    {
        int lrow = oct * 32 + (tid >> 3);    // event-local row
        int row  = base + lrow;
        int q    = tid & 7;
        int c0   = q * 8;

        float4 xi = *(const float4*)&x[row * FIN];

        float acc[8];
#pragma unroll
        for (int c = 0; c < 8; ++c) acc[c] = sb2[c0 + c];

#pragma unroll 4
        for (int j = 0; j < LATD; ++j) {
            float tj = sb1[j]
                     + xi.x * sW1[0 * LATD + j]
                     + xi.y * sW1[1 * LATD + j]
                     + xi.z * sW1[2 * LATD + j]
                     + xi.w * sW1[3 * LATD + j];
            tj = (tj > 0.0f) ? tj : 0.01f * tj;
            const float* w2r = &sW2[j * LATD + c0];
#pragma unroll
            for (int c = 0; c < 8; ++c) acc[c] += tj * w2r[c];
        }
        float* o = &hout[row * LATD + c0];
#pragma unroll
        for (int c = 0; c < 8; ++c) o[c] = acc[c];
    }

    // ---- part 2: positions for all 256 event rows (1 thread/row) -----------
    {
        int n   = tid;
        int row = base + n;
        float4 xi = *(const float4*)&x[row * FIN];
        float ax = 0.f, ay = 0.f, az = 0.f;
#pragma unroll 4
        for (int j = 0; j < LATD; ++j) {
            float tj = sb1[j]
                     + xi.x * sW1[0 * LATD + j]
                     + xi.y * sW1[1 * LATD + j]
                     + xi.z * sW1[2 * LATD + j]
                     + xi.w * sW1[3 * LATD + j];
            tj = (tj > 0.0f) ? tj : 0.01f * tj;
            const float* w2r = &sW2[j * LATD];
            ax += tj * w2r[0];
            ay += tj * w2r[1];
            az += tj * w2r[2];
        }
        px[n] = ax + sb2[0];
        py[n] = ay + sb2[1];
        pz[n] = az + sb2[2];
    }
    __syncthreads();   // positions ready; sW2 no longer needed

    // ---- part 3: kNN scan, 8 threads/query (32 candidates each) ------------
    {
        int lq  = oct * 32 + (tid >> 3);
        int sub = tid & 7;

        float bd[KK];
        int   bi[KK];
#pragma unroll
        for (int s = 0; s < KK; ++s) { bd[s] = 3.0e38f; bi[s] = 0; }

        float xi = px[lq], yi = py[lq], zi = pz[lq];

        for (int j = sub; j < PER; j += 8) {
            float dx = __fadd_rn(xi, -px[j]);
            float dy = __fadd_rn(yi, -py[j]);
            float dz = __fadd_rn(zi, -pz[j]);
            float d  = __fadd_rn(__fadd_rn(__fmul_rn(dx, dx), __fmul_rn(dy, dy)),
                                 __fmul_rn(dz, dz));
            if (j == lq) d = 3.3e38f;            // exclude self
            if (d < bd[KK - 1]) {
#pragma unroll
                for (int p = KK - 1; p >= 0; --p) {
                    bool shift = (p > 0) && (d < bd[p - 1]);
                    bool place = !shift && (d < bd[p]);
                    if (shift)      { bd[p] = bd[p - 1]; bi[p] = bi[p - 1]; }
                    else if (place) { bd[p] = d;         bi[p] = j;         }
                }
            }
        }
#pragma unroll
        for (int s = 0; s < KK; ++s) {
            mdA[tid * KK + s] = bd[s];
            miA[tid * KK + s] = (uint8_t)bi[s];
        }
    }
    __syncthreads();

    // merge round 1: 128 threads, 8 lists -> 4 per query
    if (tid < 128) {
        int q = tid >> 2, h = tid & 3;
        int ra = q * 8 + 2 * h, rb = ra + 1;
        int a = 0, b = 0;
#pragma unroll
        for (int s = 0; s < KK; ++s) {
            float da = mdA[ra * KK + a], db = mdA[rb * KK + b];
            int   ia = miA[ra * KK + a], ib = miA[rb * KK + b];
            bool takeA = (da < db) || (da == db && ia < ib);
            if (takeA) { mdB[tid * KK + s] = da; miB[tid * KK + s] = (uint8_t)ia; ++a; }
            else       { mdB[tid * KK + s] = db; miB[tid * KK + s] = (uint8_t)ib; ++b; }
        }
    }
    __syncthreads();

    // merge round 2: 64 threads, 4 lists -> 2 per query (into mdC = mdA rows)
    if (tid < 64) {
        int q = tid >> 1, h = tid & 1;
        int ra = q * 4 + 2 * h, rb = ra + 1;
        int a = 0, b = 0;
#pragma unroll
        for (int s = 0; s < KK; ++s) {
            float da = mdB[ra * KK + a], db = mdB[rb * KK + b];
            int   ia = miB[ra * KK + a], ib = miB[rb * KK + b];
            bool takeA = (da < db) || (da == db && ia < ib);
            if (takeA) { mdC[tid * KK + s] = da; miC[tid * KK + s] = (uint8_t)ia; ++a; }
            else       { mdC[tid * KK + s] = db; miC[tid * KK + s] = (uint8_t)ib; ++b; }
        }
    }
    __syncthreads();

    // merge round 3: 32 threads, final output
    if (tid < 32) {
        int gid = base + oct * 32 + tid;
        float fgid = (float)gid;
        int ra = 2 * tid, rb = 2 * tid + 1;
        int a = 0, b = 0;
#pragma unroll
        for (int s = 0; s < KK; ++s) {
            float da = mdC[ra * KK + a], db = mdC[rb * KK + b];
            int   ia = miC[ra * KK + a], ib = miC[rb * KK + b];
            bool takeA = (da < db) || (da == db && ia < ib);
            int  pick  = takeA ? ia : ib;
            if (takeA) ++a; else ++b;
            int gj = base + pick;
            int e  = gid * KK + s;
            nbr[e] = gj;
            out_ei[e]       = (float)gj;
            out_ei[NKE + e] = fgid;
        }
    }
}

// ---------------------------------------------------------------------------
// Kernel 2: GIN layer (R7 best config). 256 threads, 32 rows/block, grid 256,
// occupancy 2. Phase B 4x4 tile (a = warp broadcast from transposed mT),
// phase C / OE 4x2 tiles. FUSE_OE epilogue reuses mT (sh) and st (su).
// ---------------------------------------------------------------------------
#define MT_S 36    // mT row stride (k-major, 32 rows + pad)
#define ST_S 132   // st row stride (128 + pad)
#define SH_S 68    // sh row stride (64 + pad), aliased onto mT

template <bool FUSE_OE>
__global__ void __launch_bounds__(256, 2)
k_gin(const float* __restrict__ h_in,
      float* __restrict__ h_out,
      const int* __restrict__ nbr,
      const float* __restrict__ Wa, const float* __restrict__ ba,
      const float* __restrict__ Wb, const float* __restrict__ bb,
      const float* __restrict__ W1o, const float* __restrict__ b1o,
      const float* __restrict__ W2o, const float* __restrict__ b2o,
      float* __restrict__ xe) {
    extern __shared__ float sm[];
    float* sWa  = sm;                    // 8192
    float* sWb  = sWa + 8192;            // 8192
    float* sba  = sWb + 8192;            // 128
    float* sbb  = sba + 128;             // 64
    float* mT   = sbb + 64;              // 64*MT_S = 2304 (reused as sh 32*SH_S)
    float* st   = mT + 64 * MT_S;        // 32*ST_S = 4224 (reused as su)
    float* sW1o = st + 32 * ST_S;        // 4096 (FUSE_OE)
    float* sW2o = sW1o + 4096;           // 256
    float* sb1o = sW2o + 256;            // 64
    float* sb2o = sb1o + 64;             // 4

    int tid = threadIdx.x;
    // ---- stage weights (row-major, vectorized) -----------------------------
    {
        const float4* Wa4 = (const float4*)Wa;
        const float4* Wb4 = (const float4*)Wb;
        float4* dA = (float4*)sWa;
        float4* dB = (float4*)sWb;
#pragma unroll
        for (int i = 0; i < 8; ++i) {
            dA[tid + i * 256] = Wa4[tid + i * 256];
            dB[tid + i * 256] = Wb4[tid + i * 256];
        }
        if (tid < 128) sba[tid] = ba[tid];
        if (tid < 64)  sbb[tid] = bb[tid];
        if (FUSE_OE) {
            const float4* W1o4 = (const float4*)W1o;
            float4* d3 = (float4*)sW1o;
#pragma unroll
            for (int i = 0; i < 4; ++i) d3[tid + i * 256] = W1o4[tid + i * 256];
            sW2o[tid] = W2o[tid];        // 256 floats exactly
            if (tid < 64) sb1o[tid] = b1o[tid];
            if (tid < 4)  sb2o[tid] = b2o[tid];
        }
    }

    int base = blockIdx.x * 32;

    // ---- Gather: m = h_i + sum of 15 neighbors -> mT[k][row] ---------------
    {
        int r   = tid >> 3;              // 0..31
        int oct = tid & 7;
        int i   = base + r;
        const float4* h4 = (const float4*)h_in;
        const int* nb = &nbr[i * KK];
        float4 a0 = h4[i * 16 + oct * 2];
        float4 a1 = h4[i * 16 + oct * 2 + 1];
#pragma unroll
        for (int s = 0; s < KK; ++s) {
            int j = nb[s];
            float4 v0 = h4[j * 16 + oct * 2];
            float4 v1 = h4[j * 16 + oct * 2 + 1];
            a0.x += v0.x; a0.y += v0.y; a0.z += v0.z; a0.w += v0.w;
            a1.x += v1.x; a1.y += v1.y; a1.z += v1.z; a1.w += v1.w;
        }
        int k0 = oct * 8;
        mT[(k0 + 0) * MT_S + r] = a0.x;
        mT[(k0 + 1) * MT_S + r] = a0.y;
        mT[(k0 + 2) * MT_S + r] = a0.z;
        mT[(k0 + 3) * MT_S + r] = a0.w;
        mT[(k0 + 4) * MT_S + r] = a1.x;
        mT[(k0 + 5) * MT_S + r] = a1.y;
        mT[(k0 + 6) * MT_S + r] = a1.z;
        mT[(k0 + 7) * MT_S + r] = a1.w;
    }
    __syncthreads();

    int r0 = (tid >> 5) * 4;            // warp-uniform row base (0..28)
    int cx = tid & 31;

    // ---- Phase B: t = relu(m @ Wa + ba), thread tile 4x4 -------------------
    {
        int c0 = cx * 4;
        float acc[4][4];
#pragma unroll
        for (int i = 0; i < 4; ++i)
#pragma unroll
            for (int c = 0; c < 4; ++c) acc[i][c] = sba[c0 + c];

#pragma unroll 8
        for (int k = 0; k < 64; ++k) {
            float4 a = *(const float4*)&mT[k * MT_S + r0];     // warp broadcast
            float4 b = *(const float4*)&sWa[k * HIDD + c0];
            acc[0][0] += a.x * b.x; acc[0][1] += a.x * b.y;
            acc[0][2] += a.x * b.z; acc[0][3] += a.x * b.w;
            acc[1][0] += a.y * b.x; acc[1][1] += a.y * b.y;
            acc[1][2] += a.y * b.z; acc[1][3] += a.y * b.w;
            acc[2][0] += a.z * b.x; acc[2][1] += a.z * b.y;
            acc[2][2] += a.z * b.z; acc[2][3] += a.z * b.w;
            acc[3][0] += a.w * b.x; acc[3][1] += a.w * b.y;
            acc[3][2] += a.w * b.z; acc[3][3] += a.w * b.w;
        }
#pragma unroll
        for (int i = 0; i < 4; ++i) {
            float4 q;
            q.x = fmaxf(acc[i][0], 0.f);
            q.y = fmaxf(acc[i][1], 0.f);
            q.z = fmaxf(acc[i][2], 0.f);
            q.w = fmaxf(acc[i][3], 0.f);
            *(float4*)&st[(r0 + i) * ST_S + c0] = q;
        }
    }
    __syncthreads();

    // ---- Phase C: h_out = h_in + t @ Wb + bb, thread tile 4x2 --------------
    int c1 = cx * 2;
    {
        float acc2[4][2];
#pragma unroll
        for (int i = 0; i < 4; ++i) { acc2[i][0] = sbb[c1]; acc2[i][1] = sbb[c1 + 1]; }

#pragma unroll 4
        for (int k2 = 0; k2 < HIDD; k2 += 4) {
            float4 ar[4];
            float2 bk[4];
#pragma unroll
            for (int i = 0; i < 4; ++i) ar[i] = *(const float4*)&st[(r0 + i) * ST_S + k2];
#pragma unroll
            for (int j = 0; j < 4; ++j) bk[j] = *(const float2*)&sWb[(k2 + j) * LATD + c1];
#pragma unroll
            for (int i = 0; i < 4; ++i) {
                acc2[i][0] += ar[i].x * bk[0].x + ar[i].y * bk[1].x
                            + ar[i].z * bk[2].x + ar[i].w * bk[3].x;
                acc2[i][1] += ar[i].x * bk[0].y + ar[i].y * bk[1].y
                            + ar[i].z * bk[2].y + ar[i].w * bk[3].y;
            }
        }
#pragma unroll
        for (int i = 0; i < 4; ++i) {
            float2 hv = *(const float2*)&h_in[(base + r0 + i) * LATD + c1];
            float2 o;
            o.x = hv.x + acc2[i][0];
            o.y = hv.y + acc2[i][1];
            *(float2*)&h_out[(base + r0 + i) * LATD + c1] = o;
            if (FUSE_OE) *(float2*)&mT[(r0 + i) * SH_S + c1] = o;  // sh = mT reuse
        }
    }

    if (FUSE_OE) {
        __syncthreads();
        // ---- OE1: u = leaky(h @ W1o + b1o), thread tile 4x2 (sh=mT) --------
        float u[4][2];
#pragma unroll
        for (int i = 0; i < 4; ++i) { u[i][0] = sb1o[c1]; u[i][1] = sb1o[c1 + 1]; }
#pragma unroll 4
        for (int k = 0; k < LATD; k += 4) {
            float4 ar[4];
            float2 bk[4];
#pragma unroll
            for (int i = 0; i < 4; ++i) ar[i] = *(const float4*)&mT[(r0 + i) * SH_S + k];
#pragma unroll
            for (int j = 0; j < 4; ++j) bk[j] = *(const float2*)&sW1o[(k + j) * LATD + c1];
#pragma unroll
            for (int i = 0; i < 4; ++i) {
                u[i][0] += ar[i].x * bk[0].x + ar[i].y * bk[1].x
                         + ar[i].z * bk[2].x + ar[i].w * bk[3].x;
                u[i][1] += ar[i].x * bk[0].y + ar[i].y * bk[1].y
                         + ar[i].z * bk[2].y + ar[i].w * bk[3].y;
            }
        }
#pragma unroll
        for (int i = 0; i < 4; ++i) {
            float2 q;
            q.x = (u[i][0] > 0.f) ? u[i][0] : 0.01f * u[i][0];
            q.y = (u[i][1] > 0.f) ? u[i][1] : 0.01f * u[i][1];
            *(float2*)&st[(r0 + i) * ST_S + c1] = q;   // su = st reuse
        }
        __syncthreads();
        // ---- OE2: x_emb = u @ W2o + b2o; 128 threads = (row, feature) ------
        if (tid < 128) {
            int row = tid >> 2;
            int oc  = tid & 3;
            float a = sb2o[oc];
#pragma unroll 8
            for (int k = 0; k < LATD; ++k)
                a += st[row * ST_S + k] * sW2o[k * FOUT + oc];
            xe[(base + row) * FOUT + oc] = a;
        }
    }
}

// ---------------------------------------------------------------------------
extern "C" void kernel_launch(void* const* d_in, const int* in_sizes, int n_in,
                              void* d_out, int out_size) {
    const float* x     = (const float*)d_in[0];
    const float* W_se1 = (const float*)d_in[3];
    const float* b_se1 = (const float*)d_in[4];
    const float* W_se2 = (const float*)d_in[5];
    const float* b_se2 = (const float*)d_in[6];
    const float* W_g1a = (const float*)d_in[7];
    const float* b_g1a = (const float*)d_in[8];
    const float* W_g1b = (const float*)d_in[9];
    const float* b_g1b = (const float*)d_in[10];
    const float* W_g2a = (const float*)d_in[11];
    const float* b_g2a = (const float*)d_in[12];
    const float* W_g2b = (const float*)d_in[13];
    const float* b_g2b = (const float*)d_in[14];
    const float* W_oe1 = (const float*)d_in[15];
    const float* b_oe1 = (const float*)d_in[16];
    const float* W_oe2 = (const float*)d_in[17];
    const float* b_oe2 = (const float*)d_in[18];

    float* out    = (float*)d_out;
    float* out_h  = out;
    float* out_xe = out + XE_OFF;
    float* out_ei = out + EI_OFF;

    void *p_h0, *p_h1, *p_nbr;
    cudaGetSymbolAddress(&p_h0, g_h0);
    cudaGetSymbolAddress(&p_h1, g_h1);
    cudaGetSymbolAddress(&p_nbr, g_nbr);
    float* h0 = (float*)p_h0;
    float* h1 = (float*)p_h1;
    int*   nb = (int*)p_nbr;

    static const size_t se_smem = (size_t)SE_TOT * sizeof(float);
    static const size_t gin_smem_base =
        (size_t)(8192 + 8192 + 128 + 64 + 64 * MT_S + 32 * ST_S) * sizeof(float);
    static const size_t gin_smem_oe = gin_smem_base +
        (size_t)(4096 + 256 + 64 + 4) * sizeof(float);
    cudaFuncSetAttribute(k_gin<false>, cudaFuncAttributeMaxDynamicSharedMemorySize,
                         (int)gin_smem_base);
    cudaFuncSetAttribute(k_gin<true>, cudaFuncAttributeMaxDynamicSharedMemorySize,
                         (int)gin_smem_oe);

    // 1) fused space_emb + kNN -> h0, nbr, ei
    k_se_knn<<<GEV * 8, 256, se_smem>>>(x, W_se1, b_se1, W_se2, b_se2,
                                        h0, nb, out_ei);
    // 2) GIN layer 1: h0 -> h1
    k_gin<false><<<NN / 32, 256, gin_smem_base>>>(h0, h1, nb,
        W_g1a, b_g1a, W_g1b, b_g1b, nullptr, nullptr, nullptr, nullptr, nullptr);
    // 3) GIN layer 2 + fused out_emb: h1 -> d_out (h), x_emb -> d_out
    k_gin<true><<<NN / 32, 256, gin_smem_oe>>>(h1, out_h, nb,
        W_g2a, b_g2a, W_g2b, b_g2b, W_oe1, b_oe1, W_oe2, b_oe2, out_xe);
}

// round 13
// speedup vs baseline: 1.1406x; 1.0130x over previous
#include <cuda_runtime.h>
#include <cuda_bf16.h>
#include <stdint.h>

// Problem constants
#define NN      8192
#define GEV     32
#define PER     256      // nodes per event
#define KK      15
#define FIN     4
#define FOUT    4
#define LATD    64
#define HIDD    128

#define H_ELEMS   (NN * LATD)          // 524288
#define XE_ELEMS  (NN * FOUT)          // 32768
#define NKE       (NN * KK)            // 122880
#define XE_OFF    (H_ELEMS)
#define EI_OFF    (H_ELEMS + XE_ELEMS) // 557056

#define FULLMASK 0xffffffffu
typedef unsigned long long ull;

// Device scratch (no allocations allowed)
__device__ float g_h0[NN * LATD];
__device__ float g_h1[NN * LATD];
__device__ int   g_nbr[NN * KK];

// ---------------------------------------------------------------------------
// Kernel 1: fused space_emb + event-local kNN (warp-per-query extract-min).
// grid 256 = one CTA per 32-query octant (8 CTAs/event), 256 threads.
//  part 1: space_emb for the CTA's own 32 rows -> h0 (8 thr/row, 8 cols).
//  part 2: positions (first 3 emb cols) for ALL 256 event rows (1 thr/row).
//  part 3: kNN — 1 warp per query, 4 queries/warp sequentially. Each lane
//          owns 8 candidates as packed keys (dist_bits<<8 | idx): exact
//          (d, idx) lexicographic order == lax.top_k tie-breaking. Lane sorts
//          its 8 keys (19-CE Batcher network), then 15 divergence-free
//          warp-butterfly u64-min extraction rounds.
// ---------------------------------------------------------------------------
#define SE_W1   0            // 256 f
#define SE_B1   256          // 64 f
#define SE_B2   320          // 64 f
#define SE_W2   384          // 4096 f
#define SE_PX   4480         // 256 f
#define SE_PY   4736         // 256 f
#define SE_PZ   4992         // 256 f
#define SE_TOT  5248         // floats (~21 KB)

#define CE(i, j) { ull lo = (s##i < s##j) ? s##i : s##j; \
                   ull hi = (s##i < s##j) ? s##j : s##i; \
                   s##i = lo; s##j = hi; }

__global__ void __launch_bounds__(256, 2)
k_se_knn(const float* __restrict__ x,
         const float* __restrict__ W1, const float* __restrict__ b1,
         const float* __restrict__ W2, const float* __restrict__ b2,
         float* __restrict__ hout,
         int* __restrict__ nbr,
         float* __restrict__ out_ei) {
    extern __shared__ float sm[];
    float* sW1 = sm + SE_W1;
    float* sb1 = sm + SE_B1;
    float* sb2 = sm + SE_B2;
    float* sW2 = sm + SE_W2;
    float* px  = sm + SE_PX;
    float* py  = sm + SE_PY;
    float* pz  = sm + SE_PZ;

    int tid  = threadIdx.x;
    int ev   = blockIdx.x >> 3;
    int oct  = blockIdx.x & 7;
    int base = ev * PER;

    // ---- stage weights ------------------------------------------------------
    if (tid < FIN * LATD) sW1[tid] = W1[tid];
    if (tid < 64) sb1[tid] = b1[tid];
    if (tid < 64) sb2[tid] = b2[tid];
    {
        float4* d = (float4*)sW2;
        const float4* s = (const float4*)W2;
#pragma unroll
        for (int i = 0; i < 4; ++i) d[tid + i * 256] = s[tid + i * 256];
    }
    __syncthreads();

    // ---- part 1: space_emb for own 32 rows (8 threads/row, 8 cols each) ----
    {
        int lrow = oct * 32 + (tid >> 3);    // event-local row
        int row  = base + lrow;
        int q    = tid & 7;
        int c0   = q * 8;

        float4 xi = *(const float4*)&x[row * FIN];

        float acc[8];
#pragma unroll
        for (int c = 0; c < 8; ++c) acc[c] = sb2[c0 + c];

#pragma unroll 4
        for (int j = 0; j < LATD; ++j) {
            float tj = sb1[j]
                     + xi.x * sW1[0 * LATD + j]
                     + xi.y * sW1[1 * LATD + j]
                     + xi.z * sW1[2 * LATD + j]
                     + xi.w * sW1[3 * LATD + j];
            tj = (tj > 0.0f) ? tj : 0.01f * tj;
            float4 w0 = *(const float4*)&sW2[j * LATD + c0];
            float4 w1 = *(const float4*)&sW2[j * LATD + c0 + 4];
            acc[0] += tj * w0.x; acc[1] += tj * w0.y;
            acc[2] += tj * w0.z; acc[3] += tj * w0.w;
            acc[4] += tj * w1.x; acc[5] += tj * w1.y;
            acc[6] += tj * w1.z; acc[7] += tj * w1.w;
        }
        float* o = &hout[row * LATD + c0];
#pragma unroll
        for (int c = 0; c < 8; ++c) o[c] = acc[c];
    }

    // ---- part 2: positions for all 256 event rows (1 thread/row) -----------
    {
        int n   = tid;
        int row = base + n;
        float4 xi = *(const float4*)&x[row * FIN];
        float ax = 0.f, ay = 0.f, az = 0.f;
#pragma unroll 4
        for (int j = 0; j < LATD; ++j) {
            float tj = sb1[j]
                     + xi.x * sW1[0 * LATD + j]
                     + xi.y * sW1[1 * LATD + j]
                     + xi.z * sW1[2 * LATD + j]
                     + xi.w * sW1[3 * LATD + j];
            tj = (tj > 0.0f) ? tj : 0.01f * tj;
            const float* w2r = &sW2[j * LATD];
            ax += tj * w2r[0];
            ay += tj * w2r[1];
            az += tj * w2r[2];
        }
        px[n] = ax + sb2[0];
        py[n] = ay + sb2[1];
        pz[n] = az + sb2[2];
    }
    __syncthreads();   // positions ready

    // ---- part 3: kNN, 1 warp per query, 4 queries per warp ------------------
    {
        int warp = tid >> 5;
        int lane = tid & 31;

#pragma unroll 1
        for (int q4 = 0; q4 < 4; ++q4) {
            int lq  = oct * 32 + warp * 4 + q4;   // event-local query
            int gid = base + lq;

            float xi = px[lq], yi = py[lq], zi = pz[lq];

            // compute 8 packed keys: candidates j = lane + 32*s
            ull s0, s1, s2, s3, s4, s5, s6, s7;
            {
                ull ks[8];
#pragma unroll
                for (int s = 0; s < 8; ++s) {
                    int j = lane + 32 * s;
                    float dx = __fadd_rn(xi, -px[j]);
                    float dy = __fadd_rn(yi, -py[j]);
                    float dz = __fadd_rn(zi, -pz[j]);
                    float d  = __fadd_rn(__fadd_rn(__fmul_rn(dx, dx),
                                                   __fmul_rn(dy, dy)),
                                         __fmul_rn(dz, dz));
                    unsigned db = __float_as_uint(d);
                    if (j == lq) db = 0x7F800000u;   // +INF: exclude self
                    ks[s] = ((ull)db << 8) | (unsigned)j;
                }
                s0 = ks[0]; s1 = ks[1]; s2 = ks[2]; s3 = ks[3];
                s4 = ks[4]; s5 = ks[5]; s6 = ks[6]; s7 = ks[7];
            }

            // sort 8 ascending: Batcher odd-even network, 19 CEs
            CE(0,1) CE(2,3) CE(4,5) CE(6,7)
            CE(0,2) CE(1,3) CE(4,6) CE(5,7)
            CE(1,2) CE(5,6)
            CE(0,4) CE(1,5) CE(2,6) CE(3,7)
            CE(2,4) CE(3,5)
            CE(1,2) CE(3,4) CE(5,6)

            // 15 extract-min rounds, divergence-free
            ull keep = 0;
#pragma unroll
            for (int r = 0; r < KK; ++r) {
                ull w = s0;
#pragma unroll
                for (int off = 16; off > 0; off >>= 1) {
                    ull o = __shfl_xor_sync(FULLMASK, w, off);
                    if (o < w) w = o;
                }
                if (lane == r) keep = w;
                bool iwin = (s0 == w);
                if (iwin) {             // shift my sorted list down
                    s0 = s1; s1 = s2; s2 = s3; s3 = s4;
                    s4 = s5; s5 = s6; s6 = s7; s7 = ~0ull;
                }
            }

            // lanes 0..14 hold the k-th neighbor (in ascending order)
            if (lane < KK) {
                int jloc = (int)(keep & 0xFF);
                int gj   = base + jloc;
                int e    = gid * KK + lane;
                nbr[e] = gj;
                out_ei[e]       = (float)gj;
                out_ei[NKE + e] = (float)gid;
            }
        }
    }
}

// ---------------------------------------------------------------------------
// Kernel 2: GIN layer (best config). 256 threads, 32 rows/block, grid 256,
// occupancy 2. Phase B 4x4 tile (a = warp broadcast from transposed mT),
// phase C / OE 4x2 tiles. FUSE_OE epilogue reuses mT (sh) and st (su).
// ---------------------------------------------------------------------------
#define MT_S 36    // mT row stride (k-major, 32 rows + pad)
#define ST_S 132   // st row stride (128 + pad)
#define SH_S 68    // sh row stride (64 + pad), aliased onto mT

template <bool FUSE_OE>
__global__ void __launch_bounds__(256, 2)
k_gin(const float* __restrict__ h_in,
      float* __restrict__ h_out,
      const int* __restrict__ nbr,
      const float* __restrict__ Wa, const float* __restrict__ ba,
      const float* __restrict__ Wb, const float* __restrict__ bb,
      const float* __restrict__ W1o, const float* __restrict__ b1o,
      const float* __restrict__ W2o, const float* __restrict__ b2o,
      float* __restrict__ xe) {
    extern __shared__ float sm[];
    float* sWa  = sm;                    // 8192
    float* sWb  = sWa + 8192;            // 8192
    float* sba  = sWb + 8192;            // 128
    float* sbb  = sba + 128;             // 64
    float* mT   = sbb + 64;              // 64*MT_S = 2304 (reused as sh 32*SH_S)
    float* st   = mT + 64 * MT_S;        // 32*ST_S = 4224 (reused as su)
    float* sW1o = st + 32 * ST_S;        // 4096 (FUSE_OE)
    float* sW2o = sW1o + 4096;           // 256
    float* sb1o = sW2o + 256;            // 64
    float* sb2o = sb1o + 64;             // 4

    int tid = threadIdx.x;
    // ---- stage weights (row-major, vectorized) -----------------------------
    {
        const float4* Wa4 = (const float4*)Wa;
        const float4* Wb4 = (const float4*)Wb;
        float4* dA = (float4*)sWa;
        float4* dB = (float4*)sWb;
#pragma unroll
        for (int i = 0; i < 8; ++i) {
            dA[tid + i * 256] = Wa4[tid + i * 256];
            dB[tid + i * 256] = Wb4[tid + i * 256];
        }
        if (tid < 128) sba[tid] = ba[tid];
        if (tid < 64)  sbb[tid] = bb[tid];
        if (FUSE_OE) {
            const float4* W1o4 = (const float4*)W1o;
            float4* d3 = (float4*)sW1o;
#pragma unroll
            for (int i = 0; i < 4; ++i) d3[tid + i * 256] = W1o4[tid + i * 256];
            sW2o[tid] = W2o[tid];        // 256 floats exactly
            if (tid < 64) sb1o[tid] = b1o[tid];
            if (tid < 4)  sb2o[tid] = b2o[tid];
        }
    }

    int base = blockIdx.x * 32;

    // ---- Gather: m = h_i + sum of 15 neighbors -> mT[k][row] ---------------
    {
        int r   = tid >> 3;              // 0..31
        int oct = tid & 7;
        int i   = base + r;
        const float4* h4 = (const float4*)h_in;
        const int* nb = &nbr[i * KK];
        float4 a0 = h4[i * 16 + oct * 2];
        float4 a1 = h4[i * 16 + oct * 2 + 1];
#pragma unroll
        for (int s = 0; s < KK; ++s) {
            int j = nb[s];
            float4 v0 = h4[j * 16 + oct * 2];
            float4 v1 = h4[j * 16 + oct * 2 + 1];
            a0.x += v0.x; a0.y += v0.y; a0.z += v0.z; a0.w += v0.w;
            a1.x += v1.x; a1.y += v1.y; a1.z += v1.z; a1.w += v1.w;
        }
        int k0 = oct * 8;
        mT[(k0 + 0) * MT_S + r] = a0.x;
        mT[(k0 + 1) * MT_S + r] = a0.y;
        mT[(k0 + 2) * MT_S + r] = a0.z;
        mT[(k0 + 3) * MT_S + r] = a0.w;
        mT[(k0 + 4) * MT_S + r] = a1.x;
        mT[(k0 + 5) * MT_S + r] = a1.y;
        mT[(k0 + 6) * MT_S + r] = a1.z;
        mT[(k0 + 7) * MT_S + r] = a1.w;
    }
    __syncthreads();

    int r0 = (tid >> 5) * 4;            // warp-uniform row base (0..28)
    int cx = tid & 31;

    // ---- Phase B: t = relu(m @ Wa + ba), thread tile 4x4 -------------------
    {
        int c0 = cx * 4;
        float acc[4][4];
#pragma unroll
        for (int i = 0; i < 4; ++i)
#pragma unroll
            for (int c = 0; c < 4; ++c) acc[i][c] = sba[c0 + c];

#pragma unroll 8
        for (int k = 0; k < 64; ++k) {
            float4 a = *(const float4*)&mT[k * MT_S + r0];     // warp broadcast
            float4 b = *(const float4*)&sWa[k * HIDD + c0];
            acc[0][0] += a.x * b.x; acc[0][1] += a.x * b.y;
            acc[0][2] += a.x * b.z; acc[0][3] += a.x * b.w;
            acc[1][0] += a.y * b.x; acc[1][1] += a.y * b.y;
            acc[1][2] += a.y * b.z; acc[1][3] += a.y * b.w;
            acc[2][0] += a.z * b.x; acc[2][1] += a.z * b.y;
            acc[2][2] += a.z * b.z; acc[2][3] += a.z * b.w;
            acc[3][0] += a.w * b.x; acc[3][1] += a.w * b.y;
            acc[3][2] += a.w * b.z; acc[3][3] += a.w * b.w;
        }
#pragma unroll
        for (int i = 0; i < 4; ++i) {
            float4 q;
            q.x = fmaxf(acc[i][0], 0.f);
            q.y = fmaxf(acc[i][1], 0.f);
            q.z = fmaxf(acc[i][2], 0.f);
            q.w = fmaxf(acc[i][3], 0.f);
            *(float4*)&st[(r0 + i) * ST_S + c0] = q;
        }
    }
    __syncthreads();

    // ---- Phase C: h_out = h_in + t @ Wb + bb, thread tile 4x2 --------------
    int c1 = cx * 2;
    {
        float acc2[4][2];
#pragma unroll
        for (int i = 0; i < 4; ++i) { acc2[i][0] = sbb[c1]; acc2[i][1] = sbb[c1 + 1]; }

#pragma unroll 4
        for (int k2 = 0; k2 < HIDD; k2 += 4) {
            float4 ar[4];
            float2 bk[4];
#pragma unroll
            for (int i = 0; i < 4; ++i) ar[i] = *(const float4*)&st[(r0 + i) * ST_S + k2];
#pragma unroll
            for (int j = 0; j < 4; ++j) bk[j] = *(const float2*)&sWb[(k2 + j) * LATD + c1];
#pragma unroll
            for (int i = 0; i < 4; ++i) {
                acc2[i][0] += ar[i].x * bk[0].x + ar[i].y * bk[1].x
                            + ar[i].z * bk[2].x + ar[i].w * bk[3].x;
                acc2[i][1] += ar[i].x * bk[0].y + ar[i].y * bk[1].y
                            + ar[i].z * bk[2].y + ar[i].w * bk[3].y;
            }
        }
#pragma unroll
        for (int i = 0; i < 4; ++i) {
            float2 hv = *(const float2*)&h_in[(base + r0 + i) * LATD + c1];
            float2 o;
            o.x = hv.x + acc2[i][0];
            o.y = hv.y + acc2[i][1];
            *(float2*)&h_out[(base + r0 + i) * LATD + c1] = o;
            if (FUSE_OE) *(float2*)&mT[(r0 + i) * SH_S + c1] = o;  // sh = mT reuse
        }
    }

    if (FUSE_OE) {
        __syncthreads();
        // ---- OE1: u = leaky(h @ W1o + b1o), thread tile 4x2 (sh=mT) --------
        float u[4][2];
#pragma unroll
        for (int i = 0; i < 4; ++i) { u[i][0] = sb1o[c1]; u[i][1] = sb1o[c1 + 1]; }
#pragma unroll 4
        for (int k = 0; k < LATD; k += 4) {
            float4 ar[4];
            float2 bk[4];
#pragma unroll
            for (int i = 0; i < 4; ++i) ar[i] = *(const float4*)&mT[(r0 + i) * SH_S + k];
#pragma unroll
            for (int j = 0; j < 4; ++j) bk[j] = *(const float2*)&sW1o[(k + j) * LATD + c1];
#pragma unroll
            for (int i = 0; i < 4; ++i) {
                u[i][0] += ar[i].x * bk[0].x + ar[i].y * bk[1].x
                         + ar[i].z * bk[2].x + ar[i].w * bk[3].x;
                u[i][1] += ar[i].x * bk[0].y + ar[i].y * bk[1].y
                         + ar[i].z * bk[2].y + ar[i].w * bk[3].y;
            }
        }
#pragma unroll
        for (int i = 0; i < 4; ++i) {
            float2 q;
            q.x = (u[i][0] > 0.f) ? u[i][0] : 0.01f * u[i][0];
            q.y = (u[i][1] > 0.f) ? u[i][1] : 0.01f * u[i][1];
            *(float2*)&st[(r0 + i) * ST_S + c1] = q;   // su = st reuse
        }
        __syncthreads();
        // ---- OE2: x_emb = u @ W2o + b2o; 128 threads = (row, feature) ------
        if (tid < 128) {
            int row = tid >> 2;
            int oc  = tid & 3;
            float a = sb2o[oc];
#pragma unroll 8
            for (int k = 0; k < LATD; ++k)
                a += st[row * ST_S + k] * sW2o[k * FOUT + oc];
            xe[(base + row) * FOUT + oc] = a;
        }
    }
}

// ---------------------------------------------------------------------------
extern "C" void kernel_launch(void* const* d_in, const int* in_sizes, int n_in,
                              void* d_out, int out_size) {
    const float* x     = (const float*)d_in[0];
    const float* W_se1 = (const float*)d_in[3];
    const float* b_se1 = (const float*)d_in[4];
    const float* W_se2 = (const float*)d_in[5];
    const float* b_se2 = (const float*)d_in[6];
    const float* W_g1a = (const float*)d_in[7];
    const float* b_g1a = (const float*)d_in[8];
    const float* W_g1b = (const float*)d_in[9];
    const float* b_g1b = (const float*)d_in[10];
    const float* W_g2a = (const float*)d_in[11];
    const float* b_g2a = (const float*)d_in[12];
    const float* W_g2b = (const float*)d_in[13];
    const float* b_g2b = (const float*)d_in[14];
    const float* W_oe1 = (const float*)d_in[15];
    const float* b_oe1 = (const float*)d_in[16];
    const float* W_oe2 = (const float*)d_in[17];
    const float* b_oe2 = (const float*)d_in[18];

    float* out    = (float*)d_out;
    float* out_h  = out;
    float* out_xe = out + XE_OFF;
    float* out_ei = out + EI_OFF;

    void *p_h0, *p_h1, *p_nbr;
    cudaGetSymbolAddress(&p_h0, g_h0);
    cudaGetSymbolAddress(&p_h1, g_h1);
    cudaGetSymbolAddress(&p_nbr, g_nbr);
    float* h0 = (float*)p_h0;
    float* h1 = (float*)p_h1;
    int*   nb = (int*)p_nbr;

    static const size_t se_smem = (size_t)SE_TOT * sizeof(float);
    static const size_t gin_smem_base =
        (size_t)(8192 + 8192 + 128 + 64 + 64 * MT_S + 32 * ST_S) * sizeof(float);
    static const size_t gin_smem_oe = gin_smem_base +
        (size_t)(4096 + 256 + 64 + 4) * sizeof(float);
    cudaFuncSetAttribute(k_gin<false>, cudaFuncAttributeMaxDynamicSharedMemorySize,
                         (int)gin_smem_base);
    cudaFuncSetAttribute(k_gin<true>, cudaFuncAttributeMaxDynamicSharedMemorySize,
                         (int)gin_smem_oe);

    // 1) fused space_emb + kNN -> h0, nbr, ei
    k_se_knn<<<GEV * 8, 256, se_smem>>>(x, W_se1, b_se1, W_se2, b_se2,
                                        h0, nb, out_ei);
    // 2) GIN layer 1: h0 -> h1
    k_gin<false><<<NN / 32, 256, gin_smem_base>>>(h0, h1, nb,
        W_g1a, b_g1a, W_g1b, b_g1b, nullptr, nullptr, nullptr, nullptr, nullptr);
    // 3) GIN layer 2 + fused out_emb: h1 -> d_out (h), x_emb -> d_out
    k_gin<true><<<NN / 32, 256, gin_smem_oe>>>(h1, out_h, nb,
        W_g2a, b_g2a, W_g2b, b_g2b, W_oe1, b_oe1, W_oe2, b_oe2, out_xe);
}

// round 14
// speedup vs baseline: 1.1753x; 1.0305x over previous
#include <cuda_runtime.h>
#include <cuda_bf16.h>
#include <stdint.h>

// Problem constants
#define NN      8192
#define GEV     32
#define PER     256      // nodes per event
#define KK      15
#define FIN     4
#define FOUT    4
#define LATD    64
#define HIDD    128

#define H_ELEMS   (NN * LATD)          // 524288
#define XE_ELEMS  (NN * FOUT)          // 32768
#define NKE       (NN * KK)            // 122880
#define XE_OFF    (H_ELEMS)
#define EI_OFF    (H_ELEMS + XE_ELEMS) // 557056

#define FULLMASK 0xffffffffu
typedef unsigned long long ull;

// Device scratch (no allocations allowed)
__device__ float  g_h0[NN * LATD];
__device__ float  g_h1[NN * LATD];
__device__ int    g_nbr[NN * KK];
__device__ float4 g_pos[NN];

// ---------------------------------------------------------------------------
// Kernel 1: space_emb FFN  h = leaky(x@W1+b1)@W2+b2
// 4 threads per row, 16 output cols each. grid 128 x 256.
// q==0 threads also emit positions (cols 0..2) to g_pos for the kNN kernel.
// ---------------------------------------------------------------------------
__global__ void k_space_emb(const float* __restrict__ x,
                            const float* __restrict__ W1, const float* __restrict__ b1,
                            const float* __restrict__ W2, const float* __restrict__ b2,
                            float* __restrict__ hout,
                            float4* __restrict__ pos) {
    __shared__ float sW1[FIN * LATD];
    __shared__ float sb1[LATD];
    __shared__ float sW2[LATD * LATD];
    __shared__ float sb2[LATD];
    int tid = threadIdx.x;
    for (int i = tid; i < FIN * LATD; i += blockDim.x) sW1[i] = W1[i];
    for (int i = tid; i < LATD; i += blockDim.x) { sb1[i] = b1[i]; sb2[i] = b2[i]; }
    {
        float4* sW24 = (float4*)sW2;
        const float4* W24 = (const float4*)W2;
#pragma unroll
        for (int i = 0; i < (LATD * LATD) / 4 / 256; ++i)
            sW24[tid + i * 256] = W24[tid + i * 256];
    }
    __syncthreads();

    int row = blockIdx.x * 64 + (tid >> 2);
    int q   = tid & 3;
    int c0  = q * 16;

    float4 xi = *(const float4*)&x[row * FIN];

    float acc[16];
#pragma unroll
    for (int c = 0; c < 16; ++c) acc[c] = sb2[c0 + c];

#pragma unroll 4
    for (int j = 0; j < LATD; ++j) {
        float tj = sb1[j]
                 + xi.x * sW1[0 * LATD + j]
                 + xi.y * sW1[1 * LATD + j]
                 + xi.z * sW1[2 * LATD + j]
                 + xi.w * sW1[3 * LATD + j];
        tj = (tj > 0.0f) ? tj : 0.01f * tj;
        const float* w2r = &sW2[j * LATD + c0];
#pragma unroll
        for (int c = 0; c < 16; ++c) acc[c] += tj * w2r[c];
    }
    float* o = &hout[row * LATD + c0];
#pragma unroll
    for (int c = 0; c < 16; ++c) o[c] = acc[c];
    if (q == 0) pos[row] = make_float4(acc[0], acc[1], acc[2], 0.0f);
}

// ---------------------------------------------------------------------------
// Kernel 2: event-local kNN (k=15), 1 warp per query, 1024 threads/CTA,
// grid 256 (32 queries per CTA, 8 CTAs per event).
// Lane owns 8 candidates as packed u64 keys (dist_bits<<8 | local_idx):
// exact (d, idx) lexicographic order == lax.top_k tie-breaking. Lane sorts
// its 8 keys (19-CE Batcher network), then 15 divergence-free
// warp-butterfly u64-min extraction rounds.
// ---------------------------------------------------------------------------
#define CE(i, j) { ull lo = (s##i < s##j) ? s##i : s##j; \
                   ull hi = (s##i < s##j) ? s##j : s##i; \
                   s##i = lo; s##j = hi; }

__global__ void __launch_bounds__(1024, 1)
k_knn(const float4* __restrict__ pos,
      int* __restrict__ nbr,
      float* __restrict__ out_ei) {
    __shared__ float px[PER], py[PER], pz[PER];

    int tid  = threadIdx.x;
    int ev   = blockIdx.x >> 3;
    int oct  = blockIdx.x & 7;
    int base = ev * PER;

    if (tid < PER) {
        float4 p = pos[base + tid];
        px[tid] = p.x; py[tid] = p.y; pz[tid] = p.z;
    }
    __syncthreads();

    int warp = tid >> 5;               // 0..31 = query within octant
    int lane = tid & 31;
    int lq   = oct * 32 + warp;        // event-local query
    int gid  = base + lq;

    float xi = px[lq], yi = py[lq], zi = pz[lq];

    // 8 packed keys: candidates j = lane + 32*s
    ull s0, s1, s2, s3, s4, s5, s6, s7;
    {
        ull ks[8];
#pragma unroll
        for (int s = 0; s < 8; ++s) {
            int j = lane + 32 * s;
            float dx = __fadd_rn(xi, -px[j]);
            float dy = __fadd_rn(yi, -py[j]);
            float dz = __fadd_rn(zi, -pz[j]);
            float d  = __fadd_rn(__fadd_rn(__fmul_rn(dx, dx),
                                           __fmul_rn(dy, dy)),
                                 __fmul_rn(dz, dz));
            unsigned db = __float_as_uint(d);
            if (j == lq) db = 0x7F800000u;   // +INF: exclude self
            ks[s] = ((ull)db << 8) | (unsigned)j;
        }
        s0 = ks[0]; s1 = ks[1]; s2 = ks[2]; s3 = ks[3];
        s4 = ks[4]; s5 = ks[5]; s6 = ks[6]; s7 = ks[7];
    }

    // sort 8 ascending: Batcher odd-even network, 19 CEs
    CE(0,1) CE(2,3) CE(4,5) CE(6,7)
    CE(0,2) CE(1,3) CE(4,6) CE(5,7)
    CE(1,2) CE(5,6)
    CE(0,4) CE(1,5) CE(2,6) CE(3,7)
    CE(2,4) CE(3,5)
    CE(1,2) CE(3,4) CE(5,6)

    // 15 extract-min rounds, divergence-free
    ull keep = 0;
#pragma unroll
    for (int r = 0; r < KK; ++r) {
        ull w = s0;
#pragma unroll
        for (int off = 16; off > 0; off >>= 1) {
            ull o = __shfl_xor_sync(FULLMASK, w, off);
            if (o < w) w = o;
        }
        if (lane == r) keep = w;
        if (s0 == w) {                 // winner shifts its sorted list down
            s0 = s1; s1 = s2; s2 = s3; s3 = s4;
            s4 = s5; s5 = s6; s6 = s7; s7 = ~0ull;
        }
    }

    // lanes 0..14 hold neighbors in ascending (d, idx) order
    if (lane < KK) {
        int jloc = (int)(keep & 0xFF);
        int gj   = base + jloc;
        int e    = gid * KK + lane;
        nbr[e] = gj;
        out_ei[e]       = (float)gj;
        out_ei[NKE + e] = (float)gid;
    }
}

// ---------------------------------------------------------------------------
// Kernel 3: GIN layer (best config). 256 threads, 32 rows/block, grid 256,
// occupancy 2. Phase B 4x4 tile (a = warp broadcast from transposed mT),
// phase C / OE 4x2 tiles. FUSE_OE epilogue reuses mT (sh) and st (su).
// ---------------------------------------------------------------------------
#define MT_S 36    // mT row stride (k-major, 32 rows + pad)
#define ST_S 132   // st row stride (128 + pad)
#define SH_S 68    // sh row stride (64 + pad), aliased onto mT

template <bool FUSE_OE>
__global__ void __launch_bounds__(256, 2)
k_gin(const float* __restrict__ h_in,
      float* __restrict__ h_out,
      const int* __restrict__ nbr,
      const float* __restrict__ Wa, const float* __restrict__ ba,
      const float* __restrict__ Wb, const float* __restrict__ bb,
      const float* __restrict__ W1o, const float* __restrict__ b1o,
      const float* __restrict__ W2o, const float* __restrict__ b2o,
      float* __restrict__ xe) {
    extern __shared__ float sm[];
    float* sWa  = sm;                    // 8192
    float* sWb  = sWa + 8192;            // 8192
    float* sba  = sWb + 8192;            // 128
    float* sbb  = sba + 128;             // 64
    float* mT   = sbb + 64;              // 64*MT_S = 2304 (reused as sh 32*SH_S)
    float* st   = mT + 64 * MT_S;        // 32*ST_S = 4224 (reused as su)
    float* sW1o = st + 32 * ST_S;        // 4096 (FUSE_OE)
    float* sW2o = sW1o + 4096;           // 256
    float* sb1o = sW2o + 256;            // 64
    float* sb2o = sb1o + 64;             // 4

    int tid = threadIdx.x;
    // ---- stage weights (row-major, vectorized) -----------------------------
    {
        const float4* Wa4 = (const float4*)Wa;
        const float4* Wb4 = (const float4*)Wb;
        float4* dA = (float4*)sWa;
        float4* dB = (float4*)sWb;
#pragma unroll
        for (int i = 0; i < 8; ++i) {
            dA[tid + i * 256] = Wa4[tid + i * 256];
            dB[tid + i * 256] = Wb4[tid + i * 256];
        }
        if (tid < 128) sba[tid] = ba[tid];
        if (tid < 64)  sbb[tid] = bb[tid];
        if (FUSE_OE) {
            const float4* W1o4 = (const float4*)W1o;
            float4* d3 = (float4*)sW1o;
#pragma unroll
            for (int i = 0; i < 4; ++i) d3[tid + i * 256] = W1o4[tid + i * 256];
            sW2o[tid] = W2o[tid];        // 256 floats exactly
            if (tid < 64) sb1o[tid] = b1o[tid];
            if (tid < 4)  sb2o[tid] = b2o[tid];
        }
    }

    int base = blockIdx.x * 32;

    // ---- Gather: m = h_i + sum of 15 neighbors -> mT[k][row] ---------------
    {
        int r   = tid >> 3;              // 0..31
        int oct = tid & 7;
        int i   = base + r;
        const float4* h4 = (const float4*)h_in;
        const int* nb = &nbr[i * KK];
        float4 a0 = h4[i * 16 + oct * 2];
        float4 a1 = h4[i * 16 + oct * 2 + 1];
#pragma unroll
        for (int s = 0; s < KK; ++s) {
            int j = nb[s];
            float4 v0 = h4[j * 16 + oct * 2];
            float4 v1 = h4[j * 16 + oct * 2 + 1];
            a0.x += v0.x; a0.y += v0.y; a0.z += v0.z; a0.w += v0.w;
            a1.x += v1.x; a1.y += v1.y; a1.z += v1.z; a1.w += v1.w;
        }
        int k0 = oct * 8;
        mT[(k0 + 0) * MT_S + r] = a0.x;
        mT[(k0 + 1) * MT_S + r] = a0.y;
        mT[(k0 + 2) * MT_S + r] = a0.z;
        mT[(k0 + 3) * MT_S + r] = a0.w;
        mT[(k0 + 4) * MT_S + r] = a1.x;
        mT[(k0 + 5) * MT_S + r] = a1.y;
        mT[(k0 + 6) * MT_S + r] = a1.z;
        mT[(k0 + 7) * MT_S + r] = a1.w;
    }
    __syncthreads();

    int r0 = (tid >> 5) * 4;            // warp-uniform row base (0..28)
    int cx = tid & 31;

    // ---- Phase B: t = relu(m @ Wa + ba), thread tile 4x4 -------------------
    {
        int c0 = cx * 4;
        float acc[4][4];
#pragma unroll
        for (int i = 0; i < 4; ++i)
#pragma unroll
            for (int c = 0; c < 4; ++c) acc[i][c] = sba[c0 + c];

#pragma unroll 8
        for (int k = 0; k < 64; ++k) {
            float4 a = *(const float4*)&mT[k * MT_S + r0];     // warp broadcast
            float4 b = *(const float4*)&sWa[k * HIDD + c0];
            acc[0][0] += a.x * b.x; acc[0][1] += a.x * b.y;
            acc[0][2] += a.x * b.z; acc[0][3] += a.x * b.w;
            acc[1][0] += a.y * b.x; acc[1][1] += a.y * b.y;
            acc[1][2] += a.y * b.z; acc[1][3] += a.y * b.w;
            acc[2][0] += a.z * b.x; acc[2][1] += a.z * b.y;
            acc[2][2] += a.z * b.z; acc[2][3] += a.z * b.w;
            acc[3][0] += a.w * b.x; acc[3][1] += a.w * b.y;
            acc[3][2] += a.w * b.z; acc[3][3] += a.w * b.w;
        }
#pragma unroll
        for (int i = 0; i < 4; ++i) {
            float4 q;
            q.x = fmaxf(acc[i][0], 0.f);
            q.y = fmaxf(acc[i][1], 0.f);
            q.z = fmaxf(acc[i][2], 0.f);
            q.w = fmaxf(acc[i][3], 0.f);
            *(float4*)&st[(r0 + i) * ST_S + c0] = q;
        }
    }
    __syncthreads();

    // ---- Phase C: h_out = h_in + t @ Wb + bb, thread tile 4x2 --------------
    int c1 = cx * 2;
    {
        float acc2[4][2];
#pragma unroll
        for (int i = 0; i < 4; ++i) { acc2[i][0] = sbb[c1]; acc2[i][1] = sbb[c1 + 1]; }

#pragma unroll 4
        for (int k2 = 0; k2 < HIDD; k2 += 4) {
            float4 ar[4];
            float2 bk[4];
#pragma unroll
            for (int i = 0; i < 4; ++i) ar[i] = *(const float4*)&st[(r0 + i) * ST_S + k2];
#pragma unroll
            for (int j = 0; j < 4; ++j) bk[j] = *(const float2*)&sWb[(k2 + j) * LATD + c1];
#pragma unroll
            for (int i = 0; i < 4; ++i) {
                acc2[i][0] += ar[i].x * bk[0].x + ar[i].y * bk[1].x
                            + ar[i].z * bk[2].x + ar[i].w * bk[3].x;
                acc2[i][1] += ar[i].x * bk[0].y + ar[i].y * bk[1].y
                            + ar[i].z * bk[2].y + ar[i].w * bk[3].y;
            }
        }
#pragma unroll
        for (int i = 0; i < 4; ++i) {
            float2 hv = *(const float2*)&h_in[(base + r0 + i) * LATD + c1];
            float2 o;
            o.x = hv.x + acc2[i][0];
            o.y = hv.y + acc2[i][1];
            *(float2*)&h_out[(base + r0 + i) * LATD + c1] = o;
            if (FUSE_OE) *(float2*)&mT[(r0 + i) * SH_S + c1] = o;  // sh = mT reuse
        }
    }

    if (FUSE_OE) {
        __syncthreads();
        // ---- OE1: u = leaky(h @ W1o + b1o), thread tile 4x2 (sh=mT) --------
        float u[4][2];
#pragma unroll
        for (int i = 0; i < 4; ++i) { u[i][0] = sb1o[c1]; u[i][1] = sb1o[c1 + 1]; }
#pragma unroll 4
        for (int k = 0; k < LATD; k += 4) {
            float4 ar[4];
            float2 bk[4];
#pragma unroll
            for (int i = 0; i < 4; ++i) ar[i] = *(const float4*)&mT[(r0 + i) * SH_S + k];
#pragma unroll
            for (int j = 0; j < 4; ++j) bk[j] = *(const float2*)&sW1o[(k + j) * LATD + c1];
#pragma unroll
            for (int i = 0; i < 4; ++i) {
                u[i][0] += ar[i].x * bk[0].x + ar[i].y * bk[1].x
                         + ar[i].z * bk[2].x + ar[i].w * bk[3].x;
                u[i][1] += ar[i].x * bk[0].y + ar[i].y * bk[1].y
                         + ar[i].z * bk[2].y + ar[i].w * bk[3].y;
            }
        }
#pragma unroll
        for (int i = 0; i < 4; ++i) {
            float2 q;
            q.x = (u[i][0] > 0.f) ? u[i][0] : 0.01f * u[i][0];
            q.y = (u[i][1] > 0.f) ? u[i][1] : 0.01f * u[i][1];
            *(float2*)&st[(r0 + i) * ST_S + c1] = q;   // su = st reuse
        }
        __syncthreads();
        // ---- OE2: x_emb = u @ W2o + b2o; 128 threads = (row, feature) ------
        if (tid < 128) {
            int row = tid >> 2;
            int oc  = tid & 3;
            float a = sb2o[oc];
#pragma unroll 8
            for (int k = 0; k < LATD; ++k)
                a += st[row * ST_S + k] * sW2o[k * FOUT + oc];
            xe[(base + row) * FOUT + oc] = a;
        }
    }
}

// ---------------------------------------------------------------------------
extern "C" void kernel_launch(void* const* d_in, const int* in_sizes, int n_in,
                              void* d_out, int out_size) {
    const float* x     = (const float*)d_in[0];
    const float* W_se1 = (const float*)d_in[3];
    const float* b_se1 = (const float*)d_in[4];
    const float* W_se2 = (const float*)d_in[5];
    const float* b_se2 = (const float*)d_in[6];
    const float* W_g1a = (const float*)d_in[7];
    const float* b_g1a = (const float*)d_in[8];
    const float* W_g1b = (const float*)d_in[9];
    const float* b_g1b = (const float*)d_in[10];
    const float* W_g2a = (const float*)d_in[11];
    const float* b_g2a = (const float*)d_in[12];
    const float* W_g2b = (const float*)d_in[13];
    const float* b_g2b = (const float*)d_in[14];
    const float* W_oe1 = (const float*)d_in[15];
    const float* b_oe1 = (const float*)d_in[16];
    const float* W_oe2 = (const float*)d_in[17];
    const float* b_oe2 = (const float*)d_in[18];

    float* out    = (float*)d_out;
    float* out_h  = out;
    float* out_xe = out + XE_OFF;
    float* out_ei = out + EI_OFF;

    void *p_h0, *p_h1, *p_nbr, *p_pos;
    cudaGetSymbolAddress(&p_h0, g_h0);
    cudaGetSymbolAddress(&p_h1, g_h1);
    cudaGetSymbolAddress(&p_nbr, g_nbr);
    cudaGetSymbolAddress(&p_pos, g_pos);
    float*  h0  = (float*)p_h0;
    float*  h1  = (float*)p_h1;
    int*    nb  = (int*)p_nbr;
    float4* pos = (float4*)p_pos;

    static const size_t gin_smem_base =
        (size_t)(8192 + 8192 + 128 + 64 + 64 * MT_S + 32 * ST_S) * sizeof(float);
    static const size_t gin_smem_oe = gin_smem_base +
        (size_t)(4096 + 256 + 64 + 4) * sizeof(float);
    cudaFuncSetAttribute(k_gin<false>, cudaFuncAttributeMaxDynamicSharedMemorySize,
                         (int)gin_smem_base);
    cudaFuncSetAttribute(k_gin<true>, cudaFuncAttributeMaxDynamicSharedMemorySize,
                         (int)gin_smem_oe);

    // 1) space_emb -> h0 (+ positions)
    k_space_emb<<<NN / 64, 256>>>(x, W_se1, b_se1, W_se2, b_se2, h0, pos);
    // 2) kNN, 1 warp/query -> nbr, ei
    k_knn<<<GEV * 8, 1024>>>(pos, nb, out_ei);
    // 3) GIN layer 1: h0 -> h1
    k_gin<false><<<NN / 32, 256, gin_smem_base>>>(h0, h1, nb,
        W_g1a, b_g1a, W_g1b, b_g1b, nullptr, nullptr, nullptr, nullptr, nullptr);
    // 4) GIN layer 2 + fused out_emb: h1 -> d_out (h), x_emb -> d_out
    k_gin<true><<<NN / 32, 256, gin_smem_oe>>>(h1, out_h, nb,
        W_g2a, b_g2a, W_g2b, b_g2b, W_oe1, b_oe1, W_oe2, b_oe2, out_xe);
}